// round 10
// baseline (speedup 1.0000x reference)
#include <cuda_runtime.h>
#include <cuda_bf16.h>
#include <cstdint>

// Problem constants (fixed by the dataset)
#define NNODES   50000
#define NEDGES   500000
#define IN_DIM   384
#define HID      128
#define HEADS    4
#define HC       (HEADS * HID)     // 512
#define OUT_DIM  384
#define NEG_SLOPE 0.2f
#define EPRIME   (NEDGES + NNODES) // edges + self loops

// ---------------------------------------------------------------------------
// Scratch (static device globals; allocation inside kernel_launch is banned)
// ---------------------------------------------------------------------------
__device__ float g_bufA[(size_t)NNODES * HC];                // GEMM output h
__device__ __align__(16) __nv_bfloat16 g_Ahi[(size_t)NNODES * HC];
__device__ __align__(16) __nv_bfloat16 g_Alo[(size_t)NNODES * HC];
__device__ __align__(16) __nv_bfloat16 g_Wth[HC * HC];       // W^T hi
__device__ __align__(16) __nv_bfloat16 g_Wtl[HC * HC];       // W^T lo
__device__ float g_asrc[NNODES * HEADS];
__device__ float g_adst[NNODES * HEADS];
// CSR (by dst) of the self-loop-augmented graph
__device__ int g_deg[NNODES];
__device__ int g_rowptr[NNODES];
__device__ int g_cursor[NNODES];
__device__ int g_csrc[EPRIME];
__device__ int g_bsums[256];

// ---------------------------------------------------------------------------
// Small PTX helpers (generic sm_80+ subset only — the bench's PTX stage is
// compute_103 (no 'a'), so no tcgen05/TMA instructions may appear here.)
// ---------------------------------------------------------------------------
__device__ __forceinline__ uint32_t smem_u32(const void* p) {
    uint32_t a;
    asm("{ .reg .u64 t; cvta.to.shared.u64 t, %1; cvt.u32.u64 %0, t; }"
        : "=r"(a) : "l"(p));
    return a;
}

__device__ __forceinline__ void cp_async16(uint32_t dst, const void* src, int srcBytes) {
    asm volatile("cp.async.cg.shared.global [%0], [%1], 16, %2;"
                 :: "r"(dst), "l"(src), "r"(srcBytes));
}
#define CP_ASYNC_COMMIT() asm volatile("cp.async.commit_group;" ::: "memory")
#define CP_ASYNC_WAIT(n)  asm volatile("cp.async.wait_group %0;" :: "n"(n) : "memory")

__device__ __forceinline__ uint32_t lds32(uint32_t a) {
    uint32_t v;
    asm volatile("ld.shared.b32 %0, [%1];" : "=r"(v) : "r"(a));
    return v;
}

__device__ __forceinline__ void mma_bf16(float* c, const uint32_t* a, const uint32_t* b) {
    asm volatile(
        "mma.sync.aligned.m16n8k16.row.col.f32.bf16.bf16.f32 "
        "{%0,%1,%2,%3}, {%4,%5,%6,%7}, {%8,%9}, {%0,%1,%2,%3};"
        : "+f"(c[0]), "+f"(c[1]), "+f"(c[2]), "+f"(c[3])
        : "r"(a[0]), "r"(a[1]), "r"(a[2]), "r"(a[3]), "r"(b[0]), "r"(b[1]));
}

// ---------------------------------------------------------------------------
// bf16-split tensor-core GEMM:
//   C[M,N] = Ah@Bh^T + Ah@Bl^T + Al@Bh^T (+bias)
// Ah/Al: [M,K] bf16 row-major.  Bh/Bl: [N,K] bf16 row-major (pre-transposed W).
// Tile 128x128x32, 8 warps (warp tile 64x32), cp.async double buffer,
// scalar-LDS fragment loads, 2 blocks/SM (smem fits naturally).
// Round-10 changes vs the 918us baseline:
//  * ONE __syncthreads per K-chunk (wait -> sync -> issue next loads -> compute)
//  * fused attention-scalar epilogue: each block covers one full head
//    (N-tile 128 == head width), so a_src/a_dst per (row, head) are reduced
//    in-block from the live accumulators and stored directly (no attn kernel).
// ---------------------------------------------------------------------------
#define PITCH      80                       // bytes per 32-bf16 row (40 halves)
#define TILE_B     (128 * PITCH)            // 10240 B
#define STAGE_B    (4 * TILE_B)             // 40960 B (Ah, Al, Bh, Bl)
#define GEMM_SMEM  (2 * STAGE_B)            // 81920 B

__global__ __launch_bounds__(256)
void gemm_bf16_tc(const __nv_bfloat16* __restrict__ Ah,
                  const __nv_bfloat16* __restrict__ Al,
                  const __nv_bfloat16* __restrict__ Bh,
                  const __nv_bfloat16* __restrict__ Bl,
                  float* __restrict__ C, const float* __restrict__ bias,
                  const float* __restrict__ ws,   // att_src [HC] or null
                  const float* __restrict__ wd,   // att_dst [HC] or null
                  int M, int N, int K)
{
    extern __shared__ __align__(16) char smem[];
    const uint32_t sb = smem_u32(smem);
    const int tid  = threadIdx.x;
    const int wid  = tid >> 5, lane = tid & 31;
    const int wm   = wid >> 2, wn = wid & 3;      // warp grid 2x4
    const int g    = lane >> 2, q = lane & 3;
    const int m0   = blockIdx.y * 128, n0 = blockIdx.x * 128;
    const int KC   = K >> 5;

    auto load_chunk = [&](int kc, int st) {
        const int k0 = kc * 32;
        const uint32_t stb = sb + st * STAGE_B;
        #pragma unroll
        for (int t = 0; t < 4; t++) {
            const __nv_bfloat16* src =
                (t == 0) ? Ah : (t == 1) ? Al : (t == 2) ? Bh : Bl;
            const int  rbase = (t < 2) ? m0 : n0;
            const bool guard = (t < 2);
            const uint32_t tb = stb + t * TILE_B;
            #pragma unroll
            for (int i = 0; i < 2; i++) {
                int c   = tid + i * 256;          // 0..511 chunk id
                int row = c >> 2, cw = c & 3;     // 4 x 16B chunks per row
                int gr  = rbase + row;
                int ok  = (!guard || gr < M) ? 16 : 0;
                const __nv_bfloat16* s = src + (size_t)gr * K + k0 + cw * 8;
                cp_async16(tb + row * PITCH + cw * 16, s, ok);
            }
        }
    };

    float acc[4][4][4];
    #pragma unroll
    for (int i = 0; i < 4; i++)
        #pragma unroll
        for (int j = 0; j < 4; j++)
            #pragma unroll
            for (int r = 0; r < 4; r++) acc[i][j][r] = 0.f;

    load_chunk(0, 0);
    CP_ASYNC_COMMIT();

    for (int kc = 0; kc < KC; kc++) {
        CP_ASYNC_WAIT(0);        // chunk kc resident
        __syncthreads();         // publishes stage kc; proves compute(kc-1) done
        if (kc + 1 < KC) {
            load_chunk(kc + 1, (kc + 1) & 1);
            CP_ASYNC_COMMIT();
        }

        const uint32_t stb = sb + (kc & 1) * STAGE_B;
        const uint32_t sAh = stb;
        const uint32_t sAl = stb + TILE_B;
        const uint32_t sBh = stb + 2 * TILE_B;
        const uint32_t sBl = stb + 3 * TILE_B;

        #pragma unroll
        for (int kt = 0; kt < 2; kt++) {
            const uint32_t koff = kt * 32 + q * 4;  // bytes within row
            uint32_t ah[4][4], al[4][4], bh[4][2], bl[4][2];
            #pragma unroll
            for (int mt = 0; mt < 4; mt++) {
                uint32_t a0 = (uint32_t)((wm * 64 + mt * 16 + g) * PITCH) + koff;
                ah[mt][0] = lds32(sAh + a0);
                ah[mt][1] = lds32(sAh + a0 + 8 * PITCH);
                ah[mt][2] = lds32(sAh + a0 + 16);
                ah[mt][3] = lds32(sAh + a0 + 8 * PITCH + 16);
                al[mt][0] = lds32(sAl + a0);
                al[mt][1] = lds32(sAl + a0 + 8 * PITCH);
                al[mt][2] = lds32(sAl + a0 + 16);
                al[mt][3] = lds32(sAl + a0 + 8 * PITCH + 16);
            }
            #pragma unroll
            for (int nt = 0; nt < 4; nt++) {
                uint32_t b0 = (uint32_t)((wn * 32 + nt * 8 + g) * PITCH) + koff;
                bh[nt][0] = lds32(sBh + b0);
                bh[nt][1] = lds32(sBh + b0 + 16);
                bl[nt][0] = lds32(sBl + b0);
                bl[nt][1] = lds32(sBl + b0 + 16);
            }
            #pragma unroll
            for (int mt = 0; mt < 4; mt++)
                #pragma unroll
                for (int nt = 0; nt < 4; nt++) {
                    mma_bf16(acc[mt][nt], ah[mt], bh[nt]);
                    mma_bf16(acc[mt][nt], ah[mt], bl[nt]);
                    mma_bf16(acc[mt][nt], al[mt], bh[nt]);
                }
        }
    }

    // ---- store C (+ optional bias) ----
    #pragma unroll
    for (int mt = 0; mt < 4; mt++) {
        int r0 = m0 + wm * 64 + mt * 16 + g;
        #pragma unroll
        for (int nt = 0; nt < 4; nt++) {
            int cc = n0 + wn * 32 + nt * 8 + q * 2;
            float b0 = 0.f, b1 = 0.f;
            if (bias) { b0 = bias[cc]; b1 = bias[cc + 1]; }
            if (r0 < M) {
                float2 v = make_float2(acc[mt][nt][0] + b0, acc[mt][nt][1] + b1);
                *(float2*)(C + (size_t)r0 * N + cc) = v;
            }
            if (r0 + 8 < M) {
                float2 v = make_float2(acc[mt][nt][2] + b0, acc[mt][nt][3] + b1);
                *(float2*)(C + (size_t)(r0 + 8) * N + cc) = v;
            }
        }
    }

    // ---- fused attention scalars (GAT layers only) ----
    if (ws != nullptr) {
        __syncthreads();                        // done reading stages; reuse smem
        float* red = (float*)smem;              // [2][4][128] src/dst x wn x row
        float wsv[4][2], wdv[4][2];
        #pragma unroll
        for (int nt = 0; nt < 4; nt++) {
            int cc = n0 + wn * 32 + nt * 8 + q * 2;
            wsv[nt][0] = ws[cc];  wsv[nt][1] = ws[cc + 1];
            wdv[nt][0] = wd[cc];  wdv[nt][1] = wd[cc + 1];
        }
        #pragma unroll
        for (int mt = 0; mt < 4; mt++) {
            #pragma unroll
            for (int half = 0; half < 2; half++) {
                float ssrc = 0.f, sdst = 0.f;
                #pragma unroll
                for (int nt = 0; nt < 4; nt++) {
                    float v0 = acc[mt][nt][half * 2];
                    float v1 = acc[mt][nt][half * 2 + 1];
                    ssrc += v0 * wsv[nt][0] + v1 * wsv[nt][1];
                    sdst += v0 * wdv[nt][0] + v1 * wdv[nt][1];
                }
                ssrc += __shfl_xor_sync(0xffffffffu, ssrc, 1);
                ssrc += __shfl_xor_sync(0xffffffffu, ssrc, 2);
                sdst += __shfl_xor_sync(0xffffffffu, sdst, 1);
                sdst += __shfl_xor_sync(0xffffffffu, sdst, 2);
                if (q == 0) {
                    int rl = wm * 64 + mt * 16 + half * 8 + g;   // 0..127
                    red[(0 + wn) * 128 + rl] = ssrc;
                    red[(4 + wn) * 128 + rl] = sdst;
                }
            }
        }
        __syncthreads();
        int rl    = tid & 127;
        int which = tid >> 7;                   // 0 = src, 1 = dst
        const float* base = red + which * 4 * 128;
        float sum = base[0 * 128 + rl] + base[1 * 128 + rl]
                  + base[2 * 128 + rl] + base[3 * 128 + rl];
        int grow = m0 + rl;
        int head = n0 >> 7;                     // N-tile == head width
        if (grow < M) {
            float* dst = which ? g_adst : g_asrc;
            dst[grow * HEADS + head] = sum;
        }
    }
}

// ---------------------------------------------------------------------------
// bf16 hi/lo splits of GEMM operands (float4-vectorized; n % 4 == 0)
// ---------------------------------------------------------------------------
__global__ void split_bf16(const float* __restrict__ in,
                           __nv_bfloat16* __restrict__ hi,
                           __nv_bfloat16* __restrict__ lo, long n4)
{
    long i      = (long)blockIdx.x * blockDim.x + threadIdx.x;
    long stride = (long)gridDim.x * blockDim.x;
    for (long j = i; j < n4; j += stride) {
        float4 f = ((const float4*)in)[j];
        __nv_bfloat16 h0 = __float2bfloat16_rn(f.x);
        __nv_bfloat16 h1 = __float2bfloat16_rn(f.y);
        __nv_bfloat16 h2 = __float2bfloat16_rn(f.z);
        __nv_bfloat16 h3 = __float2bfloat16_rn(f.w);
        ((__nv_bfloat162*)hi)[j * 2]     = __nv_bfloat162{h0, h1};
        ((__nv_bfloat162*)hi)[j * 2 + 1] = __nv_bfloat162{h2, h3};
        ((__nv_bfloat162*)lo)[j * 2] = __nv_bfloat162{
            __float2bfloat16_rn(f.x - __bfloat162float(h0)),
            __float2bfloat16_rn(f.y - __bfloat162float(h1))};
        ((__nv_bfloat162*)lo)[j * 2 + 1] = __nv_bfloat162{
            __float2bfloat16_rn(f.z - __bfloat162float(h2)),
            __float2bfloat16_rn(f.w - __bfloat162float(h3))};
    }
}

// Transpose + split: W[K,N] -> T[N,K] hi/lo
__global__ void wt_split(const float* __restrict__ W,
                         __nv_bfloat16* __restrict__ Th,
                         __nv_bfloat16* __restrict__ Tl, int K, int N)
{
    int i      = blockIdx.x * blockDim.x + threadIdx.x;
    int stride = gridDim.x * blockDim.x;
    int total  = K * N;
    for (int j = i; j < total; j += stride) {
        int n = j % N, k = j / N;
        float f = W[(size_t)k * N + n];
        __nv_bfloat16 h = __float2bfloat16_rn(f);
        Th[(size_t)n * K + k] = h;
        Tl[(size_t)n * K + k] = __float2bfloat16_rn(f - __bfloat162float(h));
    }
}

// ---------------------------------------------------------------------------
// CSR construction (by dst, self loops appended)
// ---------------------------------------------------------------------------
__global__ void csr_zero()
{
    int i = blockIdx.x * blockDim.x + threadIdx.x;
    if (i < NNODES) { g_deg[i] = 0; g_cursor[i] = 0; }
}

__global__ void csr_count(const int* __restrict__ ei)
{
    int idx = blockIdx.x * blockDim.x + threadIdx.x;
    if (idx >= EPRIME) return;
    int d = (idx < NEDGES) ? ei[NEDGES + idx] : idx - NEDGES;
    atomicAdd(&g_deg[d], 1);
}

// two-level exclusive scan of g_deg -> g_rowptr (chunks of 256)
__global__ void csr_scan1()
{
    __shared__ int s[256];
    int t = threadIdx.x, idx = blockIdx.x * 256 + t;
    int val = (idx < NNODES) ? g_deg[idx] : 0;
    s[t] = val;
    __syncthreads();
    #pragma unroll
    for (int off = 1; off < 256; off <<= 1) {
        int v = (t >= off) ? s[t - off] : 0;
        __syncthreads();
        s[t] += v;
        __syncthreads();
    }
    if (idx < NNODES) g_rowptr[idx] = s[t] - val;   // exclusive within chunk
    if (t == 255) g_bsums[blockIdx.x] = s[255];
}

__global__ void csr_scan2(int nblk)
{
    __shared__ int s[256];
    int t = threadIdx.x;
    int val = (t < nblk) ? g_bsums[t] : 0;
    s[t] = val;
    __syncthreads();
    #pragma unroll
    for (int off = 1; off < 256; off <<= 1) {
        int v = (t >= off) ? s[t - off] : 0;
        __syncthreads();
        s[t] += v;
        __syncthreads();
    }
    if (t < nblk) g_bsums[t] = s[t] - val;          // exclusive chunk offsets
}

__global__ void csr_scan3()
{
    int idx = blockIdx.x * 256 + threadIdx.x;
    if (idx < NNODES) g_rowptr[idx] += g_bsums[blockIdx.x];
}

__global__ void csr_scatter(const int* __restrict__ ei)
{
    int idx = blockIdx.x * blockDim.x + threadIdx.x;
    if (idx >= EPRIME) return;
    int s, d;
    if (idx < NEDGES) { s = ei[idx]; d = ei[NEDGES + idx]; }
    else              { s = d = idx - NEDGES; }
    int slot = g_rowptr[d] + atomicAdd(&g_cursor[d], 1);
    g_csrc[slot] = s;
}

// ---------------------------------------------------------------------------
// Fused GAT aggregation: per-dst segment softmax + gather + bias + ReLU +
// bf16 hi/lo split of the result (feeding the next GEMM directly).
// One block (128 threads) per dst node; warp w handles head w; each thread
// owns 4 consecutive output columns.
// ---------------------------------------------------------------------------
#define AGG_CHUNK 64

__global__ __launch_bounds__(128)
void gat_aggregate(const float* __restrict__ h, const float* __restrict__ bias,
                   __nv_bfloat16* __restrict__ outHi,
                   __nv_bfloat16* __restrict__ outLo)
{
    __shared__ float s_alpha[HEADS][AGG_CHUNK];
    const int d    = blockIdx.x;
    const int tid  = threadIdx.x;
    const int head = tid >> 5, lane = tid & 31;
    const int beg  = g_rowptr[d];
    const int deg  = g_deg[d];
    const float adst = g_adst[d * HEADS + head];

    // pass 1: max over incident edges (lane-parallel)
    float mx = -1e30f;
    for (int e = lane; e < deg; e += 32) {
        int s = g_csrc[beg + e];
        float v = g_asrc[s * HEADS + head] + adst;
        v = v > 0.f ? v : NEG_SLOPE * v;
        mx = fmaxf(mx, v);
    }
    #pragma unroll
    for (int o = 16; o > 0; o >>= 1)
        mx = fmaxf(mx, __shfl_xor_sync(0xffffffffu, mx, o));

    // pass 2: sum of exp
    float sm = 0.f;
    for (int e = lane; e < deg; e += 32) {
        int s = g_csrc[beg + e];
        float v = g_asrc[s * HEADS + head] + adst;
        v = v > 0.f ? v : NEG_SLOPE * v;
        sm += __expf(v - mx);
    }
    #pragma unroll
    for (int o = 16; o > 0; o >>= 1)
        sm += __shfl_xor_sync(0xffffffffu, sm, o);
    const float inv = 1.f / sm;

    // pass 3: chunked alpha staging + float4 gather-accumulate
    float4 acc = make_float4(0.f, 0.f, 0.f, 0.f);
    const float* hcol = h + tid * 4;               // column offset in row
    for (int base = 0; base < deg; base += AGG_CHUNK) {
        int m = min(AGG_CHUNK, deg - base);
        for (int e = lane; e < m; e += 32) {
            int s = g_csrc[beg + base + e];
            float v = g_asrc[s * HEADS + head] + adst;
            v = v > 0.f ? v : NEG_SLOPE * v;
            s_alpha[head][e] = __expf(v - mx) * inv;
        }
        __syncwarp();
        #pragma unroll 4
        for (int e = 0; e < m; e++) {
            int s = g_csrc[beg + base + e];        // broadcast load
            float a = s_alpha[head][e];
            float4 hv = *(const float4*)(hcol + (size_t)s * HC);
            acc.x += a * hv.x;
            acc.y += a * hv.y;
            acc.z += a * hv.z;
            acc.w += a * hv.w;
        }
        __syncwarp();
    }

    // epilogue: bias + relu + bf16 split
    const float4 bv = *(const float4*)(bias + tid * 4);
    float o0 = fmaxf(acc.x + bv.x, 0.f);
    float o1 = fmaxf(acc.y + bv.y, 0.f);
    float o2 = fmaxf(acc.z + bv.z, 0.f);
    float o3 = fmaxf(acc.w + bv.w, 0.f);
    __nv_bfloat16 h0 = __float2bfloat16_rn(o0);
    __nv_bfloat16 h1 = __float2bfloat16_rn(o1);
    __nv_bfloat16 h2 = __float2bfloat16_rn(o2);
    __nv_bfloat16 h3 = __float2bfloat16_rn(o3);
    __nv_bfloat162* dh = (__nv_bfloat162*)(outHi + (size_t)d * HC + tid * 4);
    __nv_bfloat162* dl = (__nv_bfloat162*)(outLo + (size_t)d * HC + tid * 4);
    dh[0] = __nv_bfloat162{h0, h1};
    dh[1] = __nv_bfloat162{h2, h3};
    dl[0] = __nv_bfloat162{__float2bfloat16_rn(o0 - __bfloat162float(h0)),
                           __float2bfloat16_rn(o1 - __bfloat162float(h1))};
    dl[1] = __nv_bfloat162{__float2bfloat16_rn(o2 - __bfloat162float(h2)),
                           __float2bfloat16_rn(o3 - __bfloat162float(h3))};
}

// ---------------------------------------------------------------------------
// Host-side launch
// ---------------------------------------------------------------------------
extern "C" void kernel_launch(void* const* d_in, const int* in_sizes, int n_in,
                              void* d_out, int out_size)
{
    const float* x      = (const float*)d_in[0];
    const int*   ei     = (const int*)  d_in[1];
    const float* W1     = (const float*)d_in[2];
    const float* a1_src = (const float*)d_in[3];
    const float* a1_dst = (const float*)d_in[4];
    const float* b1     = (const float*)d_in[5];
    const float* W2     = (const float*)d_in[6];
    const float* a2_src = (const float*)d_in[7];
    const float* a2_dst = (const float*)d_in[8];
    const float* b2     = (const float*)d_in[9];
    const float* Wfc    = (const float*)d_in[10];
    const float* bfc    = (const float*)d_in[11];
    float* out = (float*)d_out;

    float* bufA;
    __nv_bfloat16 *Ahi, *Alo, *Wth, *Wtl;
    cudaGetSymbolAddress((void**)&bufA, g_bufA);
    cudaGetSymbolAddress((void**)&Ahi,  g_Ahi);
    cudaGetSymbolAddress((void**)&Alo,  g_Alo);
    cudaGetSymbolAddress((void**)&Wth,  g_Wth);
    cudaGetSymbolAddress((void**)&Wtl,  g_Wtl);

    cudaFuncSetAttribute(gemm_bf16_tc,
                         cudaFuncAttributeMaxDynamicSharedMemorySize, GEMM_SMEM);

    const int MB    = (NNODES + 127) / 128;       // 391
    const int eb    = (EPRIME + 255) / 256;
    const int nblk  = (NNODES + 255) / 256;       // 196 (scan chunks)

    // ---------------- Layer 1 front + CSR build interleaved ----------------
    // (keep the GEMM as the 4th launch -> ncu captures it)
    wt_split<<<256, 256>>>(W1, Wth, Wtl, IN_DIM, HC);                        // 1
    split_bf16<<<1024, 256>>>(x, Ahi, Alo, (long)NNODES * IN_DIM / 4);       // 2
    csr_zero<<<nblk, 256>>>();                                               // 3
    gemm_bf16_tc<<<dim3(HC / 128, MB), 256, GEMM_SMEM>>>(                    // 4
        Ahi, Alo, Wth, Wtl, bufA, nullptr, a1_src, a1_dst, NNODES, HC, IN_DIM);
    csr_count<<<eb, 256>>>(ei);                                              // 5
    csr_scan1<<<nblk, 256>>>();                                              // 6
    csr_scan2<<<1, 256>>>(nblk);                                             // 7
    csr_scan3<<<nblk, 256>>>();                                              // 8
    csr_scatter<<<eb, 256>>>(ei);                                            // 9
    gat_aggregate<<<NNODES, 128>>>(bufA, b1, Ahi, Alo);

    // ---------------- Layer 2 ----------------
    wt_split<<<256, 256>>>(W2, Wth, Wtl, HC, HC);
    gemm_bf16_tc<<<dim3(HC / 128, MB), 256, GEMM_SMEM>>>(
        Ahi, Alo, Wth, Wtl, bufA, nullptr, a2_src, a2_dst, NNODES, HC, HC);
    gat_aggregate<<<NNODES, 128>>>(bufA, b2, Ahi, Alo);

    // ---------------- FC head ----------------
    wt_split<<<256, 256>>>(Wfc, Wth, Wtl, HC, OUT_DIM);
    gemm_bf16_tc<<<dim3(OUT_DIM / 128, MB), 256, GEMM_SMEM>>>(
        Ahi, Alo, Wth, Wtl, out, bfc, nullptr, nullptr, NNODES, OUT_DIM, HC);
}

// round 11
// speedup vs baseline: 1.1104x; 1.1104x over previous
#include <cuda_runtime.h>
#include <cuda_bf16.h>
#include <cstdint>

// Problem constants (fixed by the dataset)
#define NNODES   50000
#define NEDGES   500000
#define IN_DIM   384
#define HID      128
#define HEADS    4
#define HC       (HEADS * HID)     // 512
#define OUT_DIM  384
#define NEG_SLOPE 0.2f
#define EPRIME   (NEDGES + NNODES) // edges + self loops

// ---------------------------------------------------------------------------
// Scratch (static device globals; allocation inside kernel_launch is banned)
// ---------------------------------------------------------------------------
__device__ float g_bufA[(size_t)NNODES * HC];                // GEMM output h
__device__ __align__(16) __nv_bfloat16 g_Ahi[(size_t)NNODES * HC];
__device__ __align__(16) __nv_bfloat16 g_Alo[(size_t)NNODES * HC];
__device__ __align__(16) __nv_bfloat16 g_Wth[HC * HC];       // W^T hi
__device__ __align__(16) __nv_bfloat16 g_Wtl[HC * HC];       // W^T lo
__device__ float g_asrc[NNODES * HEADS];
__device__ float g_adst[NNODES * HEADS];
// CSR (by dst) of the self-loop-augmented graph
__device__ int g_deg[NNODES];
__device__ int g_rowptr[NNODES];
__device__ int g_cursor[NNODES];
__device__ int g_csrc[EPRIME];
__device__ int g_bsums[256];

// ---------------------------------------------------------------------------
// Small PTX helpers (generic sm_80+ subset only — the bench's PTX stage is
// compute_103 (no 'a'), so no tcgen05/TMA instructions may appear here.)
// ---------------------------------------------------------------------------
__device__ __forceinline__ uint32_t smem_u32(const void* p) {
    uint32_t a;
    asm("{ .reg .u64 t; cvta.to.shared.u64 t, %1; cvt.u32.u64 %0, t; }"
        : "=r"(a) : "l"(p));
    return a;
}

__device__ __forceinline__ void cp_async16(uint32_t dst, const void* src, int srcBytes) {
    asm volatile("cp.async.cg.shared.global [%0], [%1], 16, %2;"
                 :: "r"(dst), "l"(src), "r"(srcBytes));
}
#define CP_ASYNC_COMMIT() asm volatile("cp.async.commit_group;" ::: "memory")
#define CP_ASYNC_WAIT(n)  asm volatile("cp.async.wait_group %0;" :: "n"(n) : "memory")

__device__ __forceinline__ uint32_t lds32(uint32_t a) {
    uint32_t v;
    asm volatile("ld.shared.b32 %0, [%1];" : "=r"(v) : "r"(a));
    return v;
}

__device__ __forceinline__ void mma_bf16(float* c, const uint32_t* a, const uint32_t* b) {
    asm volatile(
        "mma.sync.aligned.m16n8k16.row.col.f32.bf16.bf16.f32 "
        "{%0,%1,%2,%3}, {%4,%5,%6,%7}, {%8,%9}, {%0,%1,%2,%3};"
        : "+f"(c[0]), "+f"(c[1]), "+f"(c[2]), "+f"(c[3])
        : "r"(a[0]), "r"(a[1]), "r"(a[2]), "r"(a[3]), "r"(b[0]), "r"(b[1]));
}

// ---------------------------------------------------------------------------
// bf16-split tensor-core GEMM:
//   C[M,N] = Ah@Bh^T + Ah@Bl^T + Al@Bh^T (+bias)
// Ah/Al: [M,K] bf16 row-major.  Bh/Bl: [N,K] bf16 row-major (pre-transposed W).
// Tile 128x128x32, 8 warps (warp tile 64x32), cp.async double buffer,
// scalar-LDS fragment loads.
// Round-11: keep round-10's single-sync pipeline + fused attn epilogue, and
// add __launch_bounds__(256, 2) to cap regs at 128 (round-10 regression root
// cause: regs=134 -> 1 block/SM, occ 12.5%).  Round 9 proved the 128-reg cap
// compiles and runs at occ 24% with no mainloop spill.
// ---------------------------------------------------------------------------
#define PITCH      80                       // bytes per 32-bf16 row (40 halves)
#define TILE_B     (128 * PITCH)            // 10240 B
#define STAGE_B    (4 * TILE_B)             // 40960 B (Ah, Al, Bh, Bl)
#define GEMM_SMEM  (2 * STAGE_B)            // 81920 B

__global__ __launch_bounds__(256, 2)
void gemm_bf16_tc(const __nv_bfloat16* __restrict__ Ah,
                  const __nv_bfloat16* __restrict__ Al,
                  const __nv_bfloat16* __restrict__ Bh,
                  const __nv_bfloat16* __restrict__ Bl,
                  float* __restrict__ C, const float* __restrict__ bias,
                  const float* __restrict__ ws,   // att_src [HC] or null
                  const float* __restrict__ wd,   // att_dst [HC] or null
                  int M, int N, int K)
{
    extern __shared__ __align__(16) char smem[];
    const uint32_t sb = smem_u32(smem);
    const int tid  = threadIdx.x;
    const int wid  = tid >> 5, lane = tid & 31;
    const int wm   = wid >> 2, wn = wid & 3;      // warp grid 2x4
    const int g    = lane >> 2, q = lane & 3;
    const int m0   = blockIdx.y * 128, n0 = blockIdx.x * 128;
    const int KC   = K >> 5;

    auto load_chunk = [&](int kc, int st) {
        const int k0 = kc * 32;
        const uint32_t stb = sb + st * STAGE_B;
        #pragma unroll
        for (int t = 0; t < 4; t++) {
            const __nv_bfloat16* src =
                (t == 0) ? Ah : (t == 1) ? Al : (t == 2) ? Bh : Bl;
            const int  rbase = (t < 2) ? m0 : n0;
            const bool guard = (t < 2);
            const uint32_t tb = stb + t * TILE_B;
            #pragma unroll
            for (int i = 0; i < 2; i++) {
                int c   = tid + i * 256;          // 0..511 chunk id
                int row = c >> 2, cw = c & 3;     // 4 x 16B chunks per row
                int gr  = rbase + row;
                int ok  = (!guard || gr < M) ? 16 : 0;
                const __nv_bfloat16* s = src + (size_t)gr * K + k0 + cw * 8;
                cp_async16(tb + row * PITCH + cw * 16, s, ok);
            }
        }
    };

    float acc[4][4][4];
    #pragma unroll
    for (int i = 0; i < 4; i++)
        #pragma unroll
        for (int j = 0; j < 4; j++)
            #pragma unroll
            for (int r = 0; r < 4; r++) acc[i][j][r] = 0.f;

    load_chunk(0, 0);
    CP_ASYNC_COMMIT();

    for (int kc = 0; kc < KC; kc++) {
        CP_ASYNC_WAIT(0);        // chunk kc resident
        __syncthreads();         // publishes stage kc; proves compute(kc-1) done
        if (kc + 1 < KC) {
            load_chunk(kc + 1, (kc + 1) & 1);
            CP_ASYNC_COMMIT();
        }

        const uint32_t stb = sb + (kc & 1) * STAGE_B;
        const uint32_t sAh = stb;
        const uint32_t sAl = stb + TILE_B;
        const uint32_t sBh = stb + 2 * TILE_B;
        const uint32_t sBl = stb + 3 * TILE_B;

        #pragma unroll
        for (int kt = 0; kt < 2; kt++) {
            const uint32_t koff = kt * 32 + q * 4;  // bytes within row
            uint32_t ah[4][4], al[4][4], bh[4][2], bl[4][2];
            #pragma unroll
            for (int mt = 0; mt < 4; mt++) {
                uint32_t a0 = (uint32_t)((wm * 64 + mt * 16 + g) * PITCH) + koff;
                ah[mt][0] = lds32(sAh + a0);
                ah[mt][1] = lds32(sAh + a0 + 8 * PITCH);
                ah[mt][2] = lds32(sAh + a0 + 16);
                ah[mt][3] = lds32(sAh + a0 + 8 * PITCH + 16);
                al[mt][0] = lds32(sAl + a0);
                al[mt][1] = lds32(sAl + a0 + 8 * PITCH);
                al[mt][2] = lds32(sAl + a0 + 16);
                al[mt][3] = lds32(sAl + a0 + 8 * PITCH + 16);
            }
            #pragma unroll
            for (int nt = 0; nt < 4; nt++) {
                uint32_t b0 = (uint32_t)((wn * 32 + nt * 8 + g) * PITCH) + koff;
                bh[nt][0] = lds32(sBh + b0);
                bh[nt][1] = lds32(sBh + b0 + 16);
                bl[nt][0] = lds32(sBl + b0);
                bl[nt][1] = lds32(sBl + b0 + 16);
            }
            #pragma unroll
            for (int mt = 0; mt < 4; mt++)
                #pragma unroll
                for (int nt = 0; nt < 4; nt++) {
                    mma_bf16(acc[mt][nt], ah[mt], bh[nt]);
                    mma_bf16(acc[mt][nt], ah[mt], bl[nt]);
                    mma_bf16(acc[mt][nt], al[mt], bh[nt]);
                }
        }
    }

    // ---- store C (+ optional bias) ----
    #pragma unroll
    for (int mt = 0; mt < 4; mt++) {
        int r0 = m0 + wm * 64 + mt * 16 + g;
        #pragma unroll
        for (int nt = 0; nt < 4; nt++) {
            int cc = n0 + wn * 32 + nt * 8 + q * 2;
            float b0 = 0.f, b1 = 0.f;
            if (bias) { b0 = bias[cc]; b1 = bias[cc + 1]; }
            if (r0 < M) {
                float2 v = make_float2(acc[mt][nt][0] + b0, acc[mt][nt][1] + b1);
                *(float2*)(C + (size_t)r0 * N + cc) = v;
            }
            if (r0 + 8 < M) {
                float2 v = make_float2(acc[mt][nt][2] + b0, acc[mt][nt][3] + b1);
                *(float2*)(C + (size_t)(r0 + 8) * N + cc) = v;
            }
        }
    }

    // ---- fused attention scalars (GAT layers only) ----
    if (ws != nullptr) {
        __syncthreads();                        // done reading stages; reuse smem
        float* red = (float*)smem;              // [2][4][128] src/dst x wn x row
        float wsv[4][2], wdv[4][2];
        #pragma unroll
        for (int nt = 0; nt < 4; nt++) {
            int cc = n0 + wn * 32 + nt * 8 + q * 2;
            wsv[nt][0] = ws[cc];  wsv[nt][1] = ws[cc + 1];
            wdv[nt][0] = wd[cc];  wdv[nt][1] = wd[cc + 1];
        }
        #pragma unroll
        for (int mt = 0; mt < 4; mt++) {
            #pragma unroll
            for (int half = 0; half < 2; half++) {
                float ssrc = 0.f, sdst = 0.f;
                #pragma unroll
                for (int nt = 0; nt < 4; nt++) {
                    float v0 = acc[mt][nt][half * 2];
                    float v1 = acc[mt][nt][half * 2 + 1];
                    ssrc += v0 * wsv[nt][0] + v1 * wsv[nt][1];
                    sdst += v0 * wdv[nt][0] + v1 * wdv[nt][1];
                }
                ssrc += __shfl_xor_sync(0xffffffffu, ssrc, 1);
                ssrc += __shfl_xor_sync(0xffffffffu, ssrc, 2);
                sdst += __shfl_xor_sync(0xffffffffu, sdst, 1);
                sdst += __shfl_xor_sync(0xffffffffu, sdst, 2);
                if (q == 0) {
                    int rl = wm * 64 + mt * 16 + half * 8 + g;   // 0..127
                    red[(0 + wn) * 128 + rl] = ssrc;
                    red[(4 + wn) * 128 + rl] = sdst;
                }
            }
        }
        __syncthreads();
        int rl    = tid & 127;
        int which = tid >> 7;                   // 0 = src, 1 = dst
        const float* base = red + which * 4 * 128;
        float sum = base[0 * 128 + rl] + base[1 * 128 + rl]
                  + base[2 * 128 + rl] + base[3 * 128 + rl];
        int grow = m0 + rl;
        int head = n0 >> 7;                     // N-tile == head width
        if (grow < M) {
            float* dst = which ? g_adst : g_asrc;
            dst[grow * HEADS + head] = sum;
        }
    }
}

// ---------------------------------------------------------------------------
// bf16 hi/lo splits of GEMM operands (float4-vectorized; n % 4 == 0)
// ---------------------------------------------------------------------------
__global__ void split_bf16(const float* __restrict__ in,
                           __nv_bfloat16* __restrict__ hi,
                           __nv_bfloat16* __restrict__ lo, long n4)
{
    long i      = (long)blockIdx.x * blockDim.x + threadIdx.x;
    long stride = (long)gridDim.x * blockDim.x;
    for (long j = i; j < n4; j += stride) {
        float4 f = ((const float4*)in)[j];
        __nv_bfloat16 h0 = __float2bfloat16_rn(f.x);
        __nv_bfloat16 h1 = __float2bfloat16_rn(f.y);
        __nv_bfloat16 h2 = __float2bfloat16_rn(f.z);
        __nv_bfloat16 h3 = __float2bfloat16_rn(f.w);
        ((__nv_bfloat162*)hi)[j * 2]     = __nv_bfloat162{h0, h1};
        ((__nv_bfloat162*)hi)[j * 2 + 1] = __nv_bfloat162{h2, h3};
        ((__nv_bfloat162*)lo)[j * 2] = __nv_bfloat162{
            __float2bfloat16_rn(f.x - __bfloat162float(h0)),
            __float2bfloat16_rn(f.y - __bfloat162float(h1))};
        ((__nv_bfloat162*)lo)[j * 2 + 1] = __nv_bfloat162{
            __float2bfloat16_rn(f.z - __bfloat162float(h2)),
            __float2bfloat16_rn(f.w - __bfloat162float(h3))};
    }
}

// Transpose + split: W[K,N] -> T[N,K] hi/lo
__global__ void wt_split(const float* __restrict__ W,
                         __nv_bfloat16* __restrict__ Th,
                         __nv_bfloat16* __restrict__ Tl, int K, int N)
{
    int i      = blockIdx.x * blockDim.x + threadIdx.x;
    int stride = gridDim.x * blockDim.x;
    int total  = K * N;
    for (int j = i; j < total; j += stride) {
        int n = j % N, k = j / N;
        float f = W[(size_t)k * N + n];
        __nv_bfloat16 h = __float2bfloat16_rn(f);
        Th[(size_t)n * K + k] = h;
        Tl[(size_t)n * K + k] = __float2bfloat16_rn(f - __bfloat162float(h));
    }
}

// ---------------------------------------------------------------------------
// CSR construction (by dst, self loops appended)
// ---------------------------------------------------------------------------
__global__ void csr_zero()
{
    int i = blockIdx.x * blockDim.x + threadIdx.x;
    if (i < NNODES) { g_deg[i] = 0; g_cursor[i] = 0; }
}

__global__ void csr_count(const int* __restrict__ ei)
{
    int idx = blockIdx.x * blockDim.x + threadIdx.x;
    if (idx >= EPRIME) return;
    int d = (idx < NEDGES) ? ei[NEDGES + idx] : idx - NEDGES;
    atomicAdd(&g_deg[d], 1);
}

// two-level exclusive scan of g_deg -> g_rowptr (chunks of 256)
__global__ void csr_scan1()
{
    __shared__ int s[256];
    int t = threadIdx.x, idx = blockIdx.x * 256 + t;
    int val = (idx < NNODES) ? g_deg[idx] : 0;
    s[t] = val;
    __syncthreads();
    #pragma unroll
    for (int off = 1; off < 256; off <<= 1) {
        int v = (t >= off) ? s[t - off] : 0;
        __syncthreads();
        s[t] += v;
        __syncthreads();
    }
    if (idx < NNODES) g_rowptr[idx] = s[t] - val;   // exclusive within chunk
    if (t == 255) g_bsums[blockIdx.x] = s[255];
}

__global__ void csr_scan2(int nblk)
{
    __shared__ int s[256];
    int t = threadIdx.x;
    int val = (t < nblk) ? g_bsums[t] : 0;
    s[t] = val;
    __syncthreads();
    #pragma unroll
    for (int off = 1; off < 256; off <<= 1) {
        int v = (t >= off) ? s[t - off] : 0;
        __syncthreads();
        s[t] += v;
        __syncthreads();
    }
    if (t < nblk) g_bsums[t] = s[t] - val;          // exclusive chunk offsets
}

__global__ void csr_scan3()
{
    int idx = blockIdx.x * 256 + threadIdx.x;
    if (idx < NNODES) g_rowptr[idx] += g_bsums[blockIdx.x];
}

__global__ void csr_scatter(const int* __restrict__ ei)
{
    int idx = blockIdx.x * blockDim.x + threadIdx.x;
    if (idx >= EPRIME) return;
    int s, d;
    if (idx < NEDGES) { s = ei[idx]; d = ei[NEDGES + idx]; }
    else              { s = d = idx - NEDGES; }
    int slot = g_rowptr[d] + atomicAdd(&g_cursor[d], 1);
    g_csrc[slot] = s;
}

// ---------------------------------------------------------------------------
// Fused GAT aggregation: per-dst segment softmax + gather + bias + ReLU +
// bf16 hi/lo split of the result (feeding the next GEMM directly).
// One block (128 threads) per dst node; warp w handles head w; each thread
// owns 4 consecutive output columns.
// ---------------------------------------------------------------------------
#define AGG_CHUNK 64

__global__ __launch_bounds__(128)
void gat_aggregate(const float* __restrict__ h, const float* __restrict__ bias,
                   __nv_bfloat16* __restrict__ outHi,
                   __nv_bfloat16* __restrict__ outLo)
{
    __shared__ float s_alpha[HEADS][AGG_CHUNK];
    const int d    = blockIdx.x;
    const int tid  = threadIdx.x;
    const int head = tid >> 5, lane = tid & 31;
    const int beg  = g_rowptr[d];
    const int deg  = g_deg[d];
    const float adst = g_adst[d * HEADS + head];

    // pass 1: max over incident edges (lane-parallel)
    float mx = -1e30f;
    for (int e = lane; e < deg; e += 32) {
        int s = g_csrc[beg + e];
        float v = g_asrc[s * HEADS + head] + adst;
        v = v > 0.f ? v : NEG_SLOPE * v;
        mx = fmaxf(mx, v);
    }
    #pragma unroll
    for (int o = 16; o > 0; o >>= 1)
        mx = fmaxf(mx, __shfl_xor_sync(0xffffffffu, mx, o));

    // pass 2: sum of exp
    float sm = 0.f;
    for (int e = lane; e < deg; e += 32) {
        int s = g_csrc[beg + e];
        float v = g_asrc[s * HEADS + head] + adst;
        v = v > 0.f ? v : NEG_SLOPE * v;
        sm += __expf(v - mx);
    }
    #pragma unroll
    for (int o = 16; o > 0; o >>= 1)
        sm += __shfl_xor_sync(0xffffffffu, sm, o);
    const float inv = 1.f / sm;

    // pass 3: chunked alpha staging + float4 gather-accumulate
    float4 acc = make_float4(0.f, 0.f, 0.f, 0.f);
    const float* hcol = h + tid * 4;               // column offset in row
    for (int base = 0; base < deg; base += AGG_CHUNK) {
        int m = min(AGG_CHUNK, deg - base);
        for (int e = lane; e < m; e += 32) {
            int s = g_csrc[beg + base + e];
            float v = g_asrc[s * HEADS + head] + adst;
            v = v > 0.f ? v : NEG_SLOPE * v;
            s_alpha[head][e] = __expf(v - mx) * inv;
        }
        __syncwarp();
        #pragma unroll 4
        for (int e = 0; e < m; e++) {
            int s = g_csrc[beg + base + e];        // broadcast load
            float a = s_alpha[head][e];
            float4 hv = *(const float4*)(hcol + (size_t)s * HC);
            acc.x += a * hv.x;
            acc.y += a * hv.y;
            acc.z += a * hv.z;
            acc.w += a * hv.w;
        }
        __syncwarp();
    }

    // epilogue: bias + relu + bf16 split
    const float4 bv = *(const float4*)(bias + tid * 4);
    float o0 = fmaxf(acc.x + bv.x, 0.f);
    float o1 = fmaxf(acc.y + bv.y, 0.f);
    float o2 = fmaxf(acc.z + bv.z, 0.f);
    float o3 = fmaxf(acc.w + bv.w, 0.f);
    __nv_bfloat16 h0 = __float2bfloat16_rn(o0);
    __nv_bfloat16 h1 = __float2bfloat16_rn(o1);
    __nv_bfloat16 h2 = __float2bfloat16_rn(o2);
    __nv_bfloat16 h3 = __float2bfloat16_rn(o3);
    __nv_bfloat162* dh = (__nv_bfloat162*)(outHi + (size_t)d * HC + tid * 4);
    __nv_bfloat162* dl = (__nv_bfloat162*)(outLo + (size_t)d * HC + tid * 4);
    dh[0] = __nv_bfloat162{h0, h1};
    dh[1] = __nv_bfloat162{h2, h3};
    dl[0] = __nv_bfloat162{__float2bfloat16_rn(o0 - __bfloat162float(h0)),
                           __float2bfloat16_rn(o1 - __bfloat162float(h1))};
    dl[1] = __nv_bfloat162{__float2bfloat16_rn(o2 - __bfloat162float(h2)),
                           __float2bfloat16_rn(o3 - __bfloat162float(h3))};
}

// ---------------------------------------------------------------------------
// Host-side launch
// ---------------------------------------------------------------------------
extern "C" void kernel_launch(void* const* d_in, const int* in_sizes, int n_in,
                              void* d_out, int out_size)
{
    const float* x      = (const float*)d_in[0];
    const int*   ei     = (const int*)  d_in[1];
    const float* W1     = (const float*)d_in[2];
    const float* a1_src = (const float*)d_in[3];
    const float* a1_dst = (const float*)d_in[4];
    const float* b1     = (const float*)d_in[5];
    const float* W2     = (const float*)d_in[6];
    const float* a2_src = (const float*)d_in[7];
    const float* a2_dst = (const float*)d_in[8];
    const float* b2     = (const float*)d_in[9];
    const float* Wfc    = (const float*)d_in[10];
    const float* bfc    = (const float*)d_in[11];
    float* out = (float*)d_out;

    float* bufA;
    __nv_bfloat16 *Ahi, *Alo, *Wth, *Wtl;
    cudaGetSymbolAddress((void**)&bufA, g_bufA);
    cudaGetSymbolAddress((void**)&Ahi,  g_Ahi);
    cudaGetSymbolAddress((void**)&Alo,  g_Alo);
    cudaGetSymbolAddress((void**)&Wth,  g_Wth);
    cudaGetSymbolAddress((void**)&Wtl,  g_Wtl);

    cudaFuncSetAttribute(gemm_bf16_tc,
                         cudaFuncAttributeMaxDynamicSharedMemorySize, GEMM_SMEM);

    const int MB    = (NNODES + 127) / 128;       // 391
    const int eb    = (EPRIME + 255) / 256;
    const int nblk  = (NNODES + 255) / 256;       // 196 (scan chunks)

    // ---------------- Layer 1 front + CSR build interleaved ----------------
    // (keep the GEMM as the 4th launch -> ncu captures it)
    wt_split<<<256, 256>>>(W1, Wth, Wtl, IN_DIM, HC);                        // 1
    split_bf16<<<1024, 256>>>(x, Ahi, Alo, (long)NNODES * IN_DIM / 4);       // 2
    csr_zero<<<nblk, 256>>>();                                               // 3
    gemm_bf16_tc<<<dim3(HC / 128, MB), 256, GEMM_SMEM>>>(                    // 4
        Ahi, Alo, Wth, Wtl, bufA, nullptr, a1_src, a1_dst, NNODES, HC, IN_DIM);
    csr_count<<<eb, 256>>>(ei);                                              // 5
    csr_scan1<<<nblk, 256>>>();                                              // 6
    csr_scan2<<<1, 256>>>(nblk);                                             // 7
    csr_scan3<<<nblk, 256>>>();                                              // 8
    csr_scatter<<<eb, 256>>>(ei);                                            // 9
    gat_aggregate<<<NNODES, 128>>>(bufA, b1, Ahi, Alo);

    // ---------------- Layer 2 ----------------
    wt_split<<<256, 256>>>(W2, Wth, Wtl, HC, HC);
    gemm_bf16_tc<<<dim3(HC / 128, MB), 256, GEMM_SMEM>>>(
        Ahi, Alo, Wth, Wtl, bufA, nullptr, a2_src, a2_dst, NNODES, HC, HC);
    gat_aggregate<<<NNODES, 128>>>(bufA, b2, Ahi, Alo);

    // ---------------- FC head ----------------
    wt_split<<<256, 256>>>(Wfc, Wth, Wtl, HC, OUT_DIM);
    gemm_bf16_tc<<<dim3(OUT_DIM / 128, MB), 256, GEMM_SMEM>>>(
        Ahi, Alo, Wth, Wtl, out, bfc, nullptr, nullptr, NNODES, OUT_DIM, HC);
}

// round 12
// speedup vs baseline: 1.1230x; 1.0113x over previous
#include <cuda_runtime.h>
#include <cuda_bf16.h>
#include <cstdint>

// Problem constants (fixed by the dataset)
#define NNODES   50000
#define NEDGES   500000
#define IN_DIM   384
#define HID      128
#define HEADS    4
#define HC       (HEADS * HID)     // 512
#define OUT_DIM  384
#define NEG_SLOPE 0.2f
#define EPRIME   (NEDGES + NNODES) // edges + self loops

// ---------------------------------------------------------------------------
// Scratch (static device globals; allocation inside kernel_launch is banned)
// ---------------------------------------------------------------------------
__device__ float g_bufA[(size_t)NNODES * HC];                // GEMM output h
__device__ __align__(16) __nv_bfloat16 g_Ahi[(size_t)NNODES * HC];
__device__ __align__(16) __nv_bfloat16 g_Alo[(size_t)NNODES * HC];
__device__ __align__(16) __nv_bfloat16 g_Wth[HC * HC];       // W^T hi
__device__ __align__(16) __nv_bfloat16 g_Wtl[HC * HC];       // W^T lo
__device__ float g_asrc[NNODES * HEADS];
__device__ float g_adst[NNODES * HEADS];
// CSR (by dst) of the self-loop-augmented graph
__device__ int g_deg[NNODES];
__device__ int g_rowptr[NNODES];
__device__ int g_cursor[NNODES];
__device__ int g_csrc[EPRIME];
__device__ int g_bsums[256];

// ---------------------------------------------------------------------------
// Small PTX helpers (generic sm_80+ subset only — the bench's PTX stage is
// compute_103 (no 'a'), so no tcgen05/TMA instructions may appear here.)
// ---------------------------------------------------------------------------
__device__ __forceinline__ uint32_t smem_u32(const void* p) {
    uint32_t a;
    asm("{ .reg .u64 t; cvta.to.shared.u64 t, %1; cvt.u32.u64 %0, t; }"
        : "=r"(a) : "l"(p));
    return a;
}

__device__ __forceinline__ void cp_async16(uint32_t dst, const void* src, int srcBytes) {
    asm volatile("cp.async.cg.shared.global [%0], [%1], 16, %2;"
                 :: "r"(dst), "l"(src), "r"(srcBytes));
}
#define CP_ASYNC_COMMIT() asm volatile("cp.async.commit_group;" ::: "memory")
#define CP_ASYNC_WAIT(n)  asm volatile("cp.async.wait_group %0;" :: "n"(n) : "memory")

__device__ __forceinline__ uint32_t lds32(uint32_t a) {
    uint32_t v;
    asm volatile("ld.shared.b32 %0, [%1];" : "=r"(v) : "r"(a));
    return v;
}

__device__ __forceinline__ void mma_bf16(float* c, const uint32_t* a, const uint32_t* b) {
    asm volatile(
        "mma.sync.aligned.m16n8k16.row.col.f32.bf16.bf16.f32 "
        "{%0,%1,%2,%3}, {%4,%5,%6,%7}, {%8,%9}, {%0,%1,%2,%3};"
        : "+f"(c[0]), "+f"(c[1]), "+f"(c[2]), "+f"(c[3])
        : "r"(a[0]), "r"(a[1]), "r"(a[2]), "r"(a[3]), "r"(b[0]), "r"(b[1]));
}

// ---------------------------------------------------------------------------
// bf16-split tensor-core GEMM (known-best config, unchanged from round 11):
//   C[M,N] = Ah@Bh^T + Ah@Bl^T + Al@Bh^T (+bias)
// Tile 128x128x32, 8 warps, cp.async double buffer, scalar-LDS fragments,
// single __syncthreads per K-chunk, fused attn-scalar epilogue,
// __launch_bounds__(256, 2) caps regs at 128 -> 2 blocks/SM.
// ---------------------------------------------------------------------------
#define PITCH      80                       // bytes per 32-bf16 row (40 halves)
#define TILE_B     (128 * PITCH)            // 10240 B
#define STAGE_B    (4 * TILE_B)             // 40960 B (Ah, Al, Bh, Bl)
#define GEMM_SMEM  (2 * STAGE_B)            // 81920 B

__global__ __launch_bounds__(256, 2)
void gemm_bf16_tc(const __nv_bfloat16* __restrict__ Ah,
                  const __nv_bfloat16* __restrict__ Al,
                  const __nv_bfloat16* __restrict__ Bh,
                  const __nv_bfloat16* __restrict__ Bl,
                  float* __restrict__ C, const float* __restrict__ bias,
                  const float* __restrict__ ws,   // att_src [HC] or null
                  const float* __restrict__ wd,   // att_dst [HC] or null
                  int M, int N, int K)
{
    extern __shared__ __align__(16) char smem[];
    const uint32_t sb = smem_u32(smem);
    const int tid  = threadIdx.x;
    const int wid  = tid >> 5, lane = tid & 31;
    const int wm   = wid >> 2, wn = wid & 3;      // warp grid 2x4
    const int g    = lane >> 2, q = lane & 3;
    const int m0   = blockIdx.y * 128, n0 = blockIdx.x * 128;
    const int KC   = K >> 5;

    auto load_chunk = [&](int kc, int st) {
        const int k0 = kc * 32;
        const uint32_t stb = sb + st * STAGE_B;
        #pragma unroll
        for (int t = 0; t < 4; t++) {
            const __nv_bfloat16* src =
                (t == 0) ? Ah : (t == 1) ? Al : (t == 2) ? Bh : Bl;
            const int  rbase = (t < 2) ? m0 : n0;
            const bool guard = (t < 2);
            const uint32_t tb = stb + t * TILE_B;
            #pragma unroll
            for (int i = 0; i < 2; i++) {
                int c   = tid + i * 256;          // 0..511 chunk id
                int row = c >> 2, cw = c & 3;     // 4 x 16B chunks per row
                int gr  = rbase + row;
                int ok  = (!guard || gr < M) ? 16 : 0;
                const __nv_bfloat16* s = src + (size_t)gr * K + k0 + cw * 8;
                cp_async16(tb + row * PITCH + cw * 16, s, ok);
            }
        }
    };

    float acc[4][4][4];
    #pragma unroll
    for (int i = 0; i < 4; i++)
        #pragma unroll
        for (int j = 0; j < 4; j++)
            #pragma unroll
            for (int r = 0; r < 4; r++) acc[i][j][r] = 0.f;

    load_chunk(0, 0);
    CP_ASYNC_COMMIT();

    for (int kc = 0; kc < KC; kc++) {
        CP_ASYNC_WAIT(0);        // chunk kc resident
        __syncthreads();         // publishes stage kc; proves compute(kc-1) done
        if (kc + 1 < KC) {
            load_chunk(kc + 1, (kc + 1) & 1);
            CP_ASYNC_COMMIT();
        }

        const uint32_t stb = sb + (kc & 1) * STAGE_B;
        const uint32_t sAh = stb;
        const uint32_t sAl = stb + TILE_B;
        const uint32_t sBh = stb + 2 * TILE_B;
        const uint32_t sBl = stb + 3 * TILE_B;

        #pragma unroll
        for (int kt = 0; kt < 2; kt++) {
            const uint32_t koff = kt * 32 + q * 4;  // bytes within row
            uint32_t ah[4][4], al[4][4], bh[4][2], bl[4][2];
            #pragma unroll
            for (int mt = 0; mt < 4; mt++) {
                uint32_t a0 = (uint32_t)((wm * 64 + mt * 16 + g) * PITCH) + koff;
                ah[mt][0] = lds32(sAh + a0);
                ah[mt][1] = lds32(sAh + a0 + 8 * PITCH);
                ah[mt][2] = lds32(sAh + a0 + 16);
                ah[mt][3] = lds32(sAh + a0 + 8 * PITCH + 16);
                al[mt][0] = lds32(sAl + a0);
                al[mt][1] = lds32(sAl + a0 + 8 * PITCH);
                al[mt][2] = lds32(sAl + a0 + 16);
                al[mt][3] = lds32(sAl + a0 + 8 * PITCH + 16);
            }
            #pragma unroll
            for (int nt = 0; nt < 4; nt++) {
                uint32_t b0 = (uint32_t)((wn * 32 + nt * 8 + g) * PITCH) + koff;
                bh[nt][0] = lds32(sBh + b0);
                bh[nt][1] = lds32(sBh + b0 + 16);
                bl[nt][0] = lds32(sBl + b0);
                bl[nt][1] = lds32(sBl + b0 + 16);
            }
            #pragma unroll
            for (int mt = 0; mt < 4; mt++)
                #pragma unroll
                for (int nt = 0; nt < 4; nt++) {
                    mma_bf16(acc[mt][nt], ah[mt], bh[nt]);
                    mma_bf16(acc[mt][nt], ah[mt], bl[nt]);
                    mma_bf16(acc[mt][nt], al[mt], bh[nt]);
                }
        }
    }

    // ---- store C (+ optional bias) ----
    #pragma unroll
    for (int mt = 0; mt < 4; mt++) {
        int r0 = m0 + wm * 64 + mt * 16 + g;
        #pragma unroll
        for (int nt = 0; nt < 4; nt++) {
            int cc = n0 + wn * 32 + nt * 8 + q * 2;
            float b0 = 0.f, b1 = 0.f;
            if (bias) { b0 = bias[cc]; b1 = bias[cc + 1]; }
            if (r0 < M) {
                float2 v = make_float2(acc[mt][nt][0] + b0, acc[mt][nt][1] + b1);
                *(float2*)(C + (size_t)r0 * N + cc) = v;
            }
            if (r0 + 8 < M) {
                float2 v = make_float2(acc[mt][nt][2] + b0, acc[mt][nt][3] + b1);
                *(float2*)(C + (size_t)(r0 + 8) * N + cc) = v;
            }
        }
    }

    // ---- fused attention scalars (GAT layers only) ----
    if (ws != nullptr) {
        __syncthreads();                        // done reading stages; reuse smem
        float* red = (float*)smem;              // [2][4][128] src/dst x wn x row
        float wsv[4][2], wdv[4][2];
        #pragma unroll
        for (int nt = 0; nt < 4; nt++) {
            int cc = n0 + wn * 32 + nt * 8 + q * 2;
            wsv[nt][0] = ws[cc];  wsv[nt][1] = ws[cc + 1];
            wdv[nt][0] = wd[cc];  wdv[nt][1] = wd[cc + 1];
        }
        #pragma unroll
        for (int mt = 0; mt < 4; mt++) {
            #pragma unroll
            for (int half = 0; half < 2; half++) {
                float ssrc = 0.f, sdst = 0.f;
                #pragma unroll
                for (int nt = 0; nt < 4; nt++) {
                    float v0 = acc[mt][nt][half * 2];
                    float v1 = acc[mt][nt][half * 2 + 1];
                    ssrc += v0 * wsv[nt][0] + v1 * wsv[nt][1];
                    sdst += v0 * wdv[nt][0] + v1 * wdv[nt][1];
                }
                ssrc += __shfl_xor_sync(0xffffffffu, ssrc, 1);
                ssrc += __shfl_xor_sync(0xffffffffu, ssrc, 2);
                sdst += __shfl_xor_sync(0xffffffffu, sdst, 1);
                sdst += __shfl_xor_sync(0xffffffffu, sdst, 2);
                if (q == 0) {
                    int rl = wm * 64 + mt * 16 + half * 8 + g;   // 0..127
                    red[(0 + wn) * 128 + rl] = ssrc;
                    red[(4 + wn) * 128 + rl] = sdst;
                }
            }
        }
        __syncthreads();
        int rl    = tid & 127;
        int which = tid >> 7;                   // 0 = src, 1 = dst
        const float* base = red + which * 4 * 128;
        float sum = base[0 * 128 + rl] + base[1 * 128 + rl]
                  + base[2 * 128 + rl] + base[3 * 128 + rl];
        int grow = m0 + rl;
        int head = n0 >> 7;                     // N-tile == head width
        if (grow < M) {
            float* dst = which ? g_adst : g_asrc;
            dst[grow * HEADS + head] = sum;
        }
    }
}

// ---------------------------------------------------------------------------
// bf16 hi/lo splits of GEMM operands (float4-vectorized; n % 4 == 0)
// ---------------------------------------------------------------------------
__global__ void split_bf16(const float* __restrict__ in,
                           __nv_bfloat16* __restrict__ hi,
                           __nv_bfloat16* __restrict__ lo, long n4)
{
    long i      = (long)blockIdx.x * blockDim.x + threadIdx.x;
    long stride = (long)gridDim.x * blockDim.x;
    for (long j = i; j < n4; j += stride) {
        float4 f = ((const float4*)in)[j];
        __nv_bfloat16 h0 = __float2bfloat16_rn(f.x);
        __nv_bfloat16 h1 = __float2bfloat16_rn(f.y);
        __nv_bfloat16 h2 = __float2bfloat16_rn(f.z);
        __nv_bfloat16 h3 = __float2bfloat16_rn(f.w);
        ((__nv_bfloat162*)hi)[j * 2]     = __nv_bfloat162{h0, h1};
        ((__nv_bfloat162*)hi)[j * 2 + 1] = __nv_bfloat162{h2, h3};
        ((__nv_bfloat162*)lo)[j * 2] = __nv_bfloat162{
            __float2bfloat16_rn(f.x - __bfloat162float(h0)),
            __float2bfloat16_rn(f.y - __bfloat162float(h1))};
        ((__nv_bfloat162*)lo)[j * 2 + 1] = __nv_bfloat162{
            __float2bfloat16_rn(f.z - __bfloat162float(h2)),
            __float2bfloat16_rn(f.w - __bfloat162float(h3))};
    }
}

// Transpose + split: W[K,N] -> T[N,K] hi/lo
__global__ void wt_split(const float* __restrict__ W,
                         __nv_bfloat16* __restrict__ Th,
                         __nv_bfloat16* __restrict__ Tl, int K, int N)
{
    int i      = blockIdx.x * blockDim.x + threadIdx.x;
    int stride = gridDim.x * blockDim.x;
    int total  = K * N;
    for (int j = i; j < total; j += stride) {
        int n = j % N, k = j / N;
        float f = W[(size_t)k * N + n];
        __nv_bfloat16 h = __float2bfloat16_rn(f);
        Th[(size_t)n * K + k] = h;
        Tl[(size_t)n * K + k] = __float2bfloat16_rn(f - __bfloat162float(h));
    }
}

// ---------------------------------------------------------------------------
// CSR construction (by dst, self loops appended)
// ---------------------------------------------------------------------------
__global__ void csr_zero()
{
    int i = blockIdx.x * blockDim.x + threadIdx.x;
    if (i < NNODES) { g_deg[i] = 0; g_cursor[i] = 0; }
}

__global__ void csr_count(const int* __restrict__ ei)
{
    int idx = blockIdx.x * blockDim.x + threadIdx.x;
    if (idx >= EPRIME) return;
    int d = (idx < NEDGES) ? ei[NEDGES + idx] : idx - NEDGES;
    atomicAdd(&g_deg[d], 1);
}

// two-level exclusive scan of g_deg -> g_rowptr (chunks of 256)
__global__ void csr_scan1()
{
    __shared__ int s[256];
    int t = threadIdx.x, idx = blockIdx.x * 256 + t;
    int val = (idx < NNODES) ? g_deg[idx] : 0;
    s[t] = val;
    __syncthreads();
    #pragma unroll
    for (int off = 1; off < 256; off <<= 1) {
        int v = (t >= off) ? s[t - off] : 0;
        __syncthreads();
        s[t] += v;
        __syncthreads();
    }
    if (idx < NNODES) g_rowptr[idx] = s[t] - val;   // exclusive within chunk
    if (t == 255) g_bsums[blockIdx.x] = s[255];
}

__global__ void csr_scan2(int nblk)
{
    __shared__ int s[256];
    int t = threadIdx.x;
    int val = (t < nblk) ? g_bsums[t] : 0;
    s[t] = val;
    __syncthreads();
    #pragma unroll
    for (int off = 1; off < 256; off <<= 1) {
        int v = (t >= off) ? s[t - off] : 0;
        __syncthreads();
        s[t] += v;
        __syncthreads();
    }
    if (t < nblk) g_bsums[t] = s[t] - val;          // exclusive chunk offsets
}

__global__ void csr_scan3()
{
    int idx = blockIdx.x * 256 + threadIdx.x;
    if (idx < NNODES) g_rowptr[idx] += g_bsums[blockIdx.x];
}

__global__ void csr_scatter(const int* __restrict__ ei)
{
    int idx = blockIdx.x * blockDim.x + threadIdx.x;
    if (idx >= EPRIME) return;
    int s, d;
    if (idx < NEDGES) { s = ei[idx]; d = ei[NEDGES + idx]; }
    else              { s = d = idx - NEDGES; }
    int slot = g_rowptr[d] + atomicAdd(&g_cursor[d], 1);
    g_csrc[slot] = s;
}

// ---------------------------------------------------------------------------
// Fused GAT aggregation: per-dst segment softmax + gather + bias + ReLU +
// bf16 hi/lo split of the result (feeding the next GEMM directly).
// One block (128 threads) per dst node; warp w handles head w; each thread
// owns 4 consecutive output columns.
// Round-12: register-cached single-pass softmax.  For deg <= 96 (3 edges per
// lane) the (src, v) pairs are loaded ONCE into registers; max/sum/alpha all
// computed from registers; the gather loop broadcasts (s, alpha) via shfl.
// Eliminates 2 of 3 scattered g_csrc/g_asrc gather passes + all smem staging.
// Generic fallback path handles deg > 96.
// ---------------------------------------------------------------------------
#define AGG_CHUNK 64

__global__ __launch_bounds__(128)
void gat_aggregate(const float* __restrict__ h, const float* __restrict__ bias,
                   __nv_bfloat16* __restrict__ outHi,
                   __nv_bfloat16* __restrict__ outLo)
{
    __shared__ float s_alpha[HEADS][AGG_CHUNK];
    const int d    = blockIdx.x;
    const int tid  = threadIdx.x;
    const int head = tid >> 5, lane = tid & 31;
    const int beg  = g_rowptr[d];
    const int deg  = g_deg[d];
    const float adst = g_adst[d * HEADS + head];

    float4 acc = make_float4(0.f, 0.f, 0.f, 0.f);
    const float* hcol = h + tid * 4;               // column offset in row

    if (deg <= 96) {
        // ---- fast path: everything in registers, single gather pass ----
        int   se[3];
        float ve[3];
        #pragma unroll
        for (int c = 0; c < 3; c++) {
            int e = c * 32 + lane;
            if (e < deg) {
                int s = g_csrc[beg + e];
                float v = g_asrc[s * HEADS + head] + adst;
                ve[c] = v > 0.f ? v : NEG_SLOPE * v;
                se[c] = s;
            } else {
                se[c] = 0;
                ve[c] = -1e30f;
            }
        }
        float mx = fmaxf(ve[0], fmaxf(ve[1], ve[2]));
        #pragma unroll
        for (int o = 16; o > 0; o >>= 1)
            mx = fmaxf(mx, __shfl_xor_sync(0xffffffffu, mx, o));

        float ae[3];
        float sm = 0.f;
        #pragma unroll
        for (int c = 0; c < 3; c++) {
            float a = (c * 32 + lane < deg) ? __expf(ve[c] - mx) : 0.f;
            ae[c] = a;
            sm += a;
        }
        #pragma unroll
        for (int o = 16; o > 0; o >>= 1)
            sm += __shfl_xor_sync(0xffffffffu, sm, o);
        const float inv = 1.f / sm;

        #pragma unroll
        for (int c = 0; c < 3; c++) {
            int base = c * 32;
            if (base >= deg) break;
            int m = min(32, deg - base);
            int   sc = se[c];
            float ac = ae[c];
            #pragma unroll 4
            for (int l = 0; l < m; l++) {
                int   s = __shfl_sync(0xffffffffu, sc, l);
                float a = __shfl_sync(0xffffffffu, ac, l) * inv;
                float4 hv = *(const float4*)(hcol + (size_t)s * HC);
                acc.x += a * hv.x;
                acc.y += a * hv.y;
                acc.z += a * hv.z;
                acc.w += a * hv.w;
            }
        }
    } else {
        // ---- generic path (rare): 3-pass with smem alpha staging ----
        float mx = -1e30f;
        for (int e = lane; e < deg; e += 32) {
            int s = g_csrc[beg + e];
            float v = g_asrc[s * HEADS + head] + adst;
            v = v > 0.f ? v : NEG_SLOPE * v;
            mx = fmaxf(mx, v);
        }
        #pragma unroll
        for (int o = 16; o > 0; o >>= 1)
            mx = fmaxf(mx, __shfl_xor_sync(0xffffffffu, mx, o));

        float sm = 0.f;
        for (int e = lane; e < deg; e += 32) {
            int s = g_csrc[beg + e];
            float v = g_asrc[s * HEADS + head] + adst;
            v = v > 0.f ? v : NEG_SLOPE * v;
            sm += __expf(v - mx);
        }
        #pragma unroll
        for (int o = 16; o > 0; o >>= 1)
            sm += __shfl_xor_sync(0xffffffffu, sm, o);
        const float inv = 1.f / sm;

        for (int base = 0; base < deg; base += AGG_CHUNK) {
            int m = min(AGG_CHUNK, deg - base);
            for (int e = lane; e < m; e += 32) {
                int s = g_csrc[beg + base + e];
                float v = g_asrc[s * HEADS + head] + adst;
                v = v > 0.f ? v : NEG_SLOPE * v;
                s_alpha[head][e] = __expf(v - mx) * inv;
            }
            __syncwarp();
            #pragma unroll 4
            for (int e = 0; e < m; e++) {
                int s = g_csrc[beg + base + e];
                float a = s_alpha[head][e];
                float4 hv = *(const float4*)(hcol + (size_t)s * HC);
                acc.x += a * hv.x;
                acc.y += a * hv.y;
                acc.z += a * hv.z;
                acc.w += a * hv.w;
            }
            __syncwarp();
        }
    }

    // epilogue: bias + relu + bf16 split
    const float4 bv = *(const float4*)(bias + tid * 4);
    float o0 = fmaxf(acc.x + bv.x, 0.f);
    float o1 = fmaxf(acc.y + bv.y, 0.f);
    float o2 = fmaxf(acc.z + bv.z, 0.f);
    float o3 = fmaxf(acc.w + bv.w, 0.f);
    __nv_bfloat16 h0 = __float2bfloat16_rn(o0);
    __nv_bfloat16 h1 = __float2bfloat16_rn(o1);
    __nv_bfloat16 h2 = __float2bfloat16_rn(o2);
    __nv_bfloat16 h3 = __float2bfloat16_rn(o3);
    __nv_bfloat162* dh = (__nv_bfloat162*)(outHi + (size_t)d * HC + tid * 4);
    __nv_bfloat162* dl = (__nv_bfloat162*)(outLo + (size_t)d * HC + tid * 4);
    dh[0] = __nv_bfloat162{h0, h1};
    dh[1] = __nv_bfloat162{h2, h3};
    dl[0] = __nv_bfloat162{__float2bfloat16_rn(o0 - __bfloat162float(h0)),
                           __float2bfloat16_rn(o1 - __bfloat162float(h1))};
    dl[1] = __nv_bfloat162{__float2bfloat16_rn(o2 - __bfloat162float(h2)),
                           __float2bfloat16_rn(o3 - __bfloat162float(h3))};
}

// ---------------------------------------------------------------------------
// Host-side launch
// ---------------------------------------------------------------------------
extern "C" void kernel_launch(void* const* d_in, const int* in_sizes, int n_in,
                              void* d_out, int out_size)
{
    const float* x      = (const float*)d_in[0];
    const int*   ei     = (const int*)  d_in[1];
    const float* W1     = (const float*)d_in[2];
    const float* a1_src = (const float*)d_in[3];
    const float* a1_dst = (const float*)d_in[4];
    const float* b1     = (const float*)d_in[5];
    const float* W2     = (const float*)d_in[6];
    const float* a2_src = (const float*)d_in[7];
    const float* a2_dst = (const float*)d_in[8];
    const float* b2     = (const float*)d_in[9];
    const float* Wfc    = (const float*)d_in[10];
    const float* bfc    = (const float*)d_in[11];
    float* out = (float*)d_out;

    float* bufA;
    __nv_bfloat16 *Ahi, *Alo, *Wth, *Wtl;
    cudaGetSymbolAddress((void**)&bufA, g_bufA);
    cudaGetSymbolAddress((void**)&Ahi,  g_Ahi);
    cudaGetSymbolAddress((void**)&Alo,  g_Alo);
    cudaGetSymbolAddress((void**)&Wth,  g_Wth);
    cudaGetSymbolAddress((void**)&Wtl,  g_Wtl);

    cudaFuncSetAttribute(gemm_bf16_tc,
                         cudaFuncAttributeMaxDynamicSharedMemorySize, GEMM_SMEM);

    const int MB    = (NNODES + 127) / 128;       // 391
    const int eb    = (EPRIME + 255) / 256;
    const int nblk  = (NNODES + 255) / 256;       // 196 (scan chunks)

    // ---------------- Layer 1 front + CSR build interleaved ----------------
    // (keep the GEMM as the 4th launch -> ncu captures it)
    wt_split<<<256, 256>>>(W1, Wth, Wtl, IN_DIM, HC);                        // 1
    split_bf16<<<1024, 256>>>(x, Ahi, Alo, (long)NNODES * IN_DIM / 4);       // 2
    csr_zero<<<nblk, 256>>>();                                               // 3
    gemm_bf16_tc<<<dim3(HC / 128, MB), 256, GEMM_SMEM>>>(                    // 4
        Ahi, Alo, Wth, Wtl, bufA, nullptr, a1_src, a1_dst, NNODES, HC, IN_DIM);
    csr_count<<<eb, 256>>>(ei);                                              // 5
    csr_scan1<<<nblk, 256>>>();                                              // 6
    csr_scan2<<<1, 256>>>(nblk);                                             // 7
    csr_scan3<<<nblk, 256>>>();                                              // 8
    csr_scatter<<<eb, 256>>>(ei);                                            // 9
    gat_aggregate<<<NNODES, 128>>>(bufA, b1, Ahi, Alo);

    // ---------------- Layer 2 ----------------
    wt_split<<<256, 256>>>(W2, Wth, Wtl, HC, HC);
    gemm_bf16_tc<<<dim3(HC / 128, MB), 256, GEMM_SMEM>>>(
        Ahi, Alo, Wth, Wtl, bufA, nullptr, a2_src, a2_dst, NNODES, HC, HC);
    gat_aggregate<<<NNODES, 128>>>(bufA, b2, Ahi, Alo);

    // ---------------- FC head ----------------
    wt_split<<<256, 256>>>(Wfc, Wth, Wtl, HC, OUT_DIM);
    gemm_bf16_tc<<<dim3(OUT_DIM / 128, MB), 256, GEMM_SMEM>>>(
        Ahi, Alo, Wth, Wtl, out, bfc, nullptr, nullptr, NNODES, OUT_DIM, HC);
}

// round 13
// speedup vs baseline: 1.1281x; 1.0045x over previous
#include <cuda_runtime.h>
#include <cuda_bf16.h>
#include <cstdint>

// Problem constants (fixed by the dataset)
#define NNODES   50000
#define NEDGES   500000
#define IN_DIM   384
#define HID      128
#define HEADS    4
#define HC       (HEADS * HID)     // 512
#define OUT_DIM  384
#define NEG_SLOPE 0.2f
#define EPRIME   (NEDGES + NNODES) // edges + self loops

// ---------------------------------------------------------------------------
// Scratch (static device globals; allocation inside kernel_launch is banned)
// ---------------------------------------------------------------------------
__device__ float g_bufA[(size_t)NNODES * HC];                // GEMM output h
__device__ __align__(16) __nv_bfloat16 g_Ahi[(size_t)NNODES * HC];
__device__ __align__(16) __nv_bfloat16 g_Alo[(size_t)NNODES * HC];
// per-layer transposed weights (hi/lo)
__device__ __align__(16) __nv_bfloat16 g_Wth1[HC * IN_DIM];
__device__ __align__(16) __nv_bfloat16 g_Wtl1[HC * IN_DIM];
__device__ __align__(16) __nv_bfloat16 g_Wth2[HC * HC];
__device__ __align__(16) __nv_bfloat16 g_Wtl2[HC * HC];
__device__ __align__(16) __nv_bfloat16 g_Wthf[OUT_DIM * HC];
__device__ __align__(16) __nv_bfloat16 g_Wtlf[OUT_DIM * HC];
__device__ float g_asrc[NNODES * HEADS];
__device__ float g_adst[NNODES * HEADS];
// CSR (by dst) of the self-loop-augmented graph
__device__ int g_deg[NNODES];
__device__ int g_rowptr[NNODES];
__device__ int g_cursor[NNODES];
__device__ int g_csrc[EPRIME];
__device__ int g_bsums[256];

// ---------------------------------------------------------------------------
// Small PTX helpers (generic sm_80+ subset only — the bench's PTX stage is
// compute_103 (no 'a'), so no tcgen05/TMA instructions may appear here.)
// ---------------------------------------------------------------------------
__device__ __forceinline__ uint32_t smem_u32(const void* p) {
    uint32_t a;
    asm("{ .reg .u64 t; cvta.to.shared.u64 t, %1; cvt.u32.u64 %0, t; }"
        : "=r"(a) : "l"(p));
    return a;
}

__device__ __forceinline__ void cp_async16(uint32_t dst, const void* src, int srcBytes) {
    asm volatile("cp.async.cg.shared.global [%0], [%1], 16, %2;"
                 :: "r"(dst), "l"(src), "r"(srcBytes));
}
#define CP_ASYNC_COMMIT() asm volatile("cp.async.commit_group;" ::: "memory")
#define CP_ASYNC_WAIT(n)  asm volatile("cp.async.wait_group %0;" :: "n"(n) : "memory")

__device__ __forceinline__ uint32_t lds32(uint32_t a) {
    uint32_t v;
    asm volatile("ld.shared.b32 %0, [%1];" : "=r"(v) : "r"(a));
    return v;
}

__device__ __forceinline__ void mma_bf16(float* c, const uint32_t* a, const uint32_t* b) {
    asm volatile(
        "mma.sync.aligned.m16n8k16.row.col.f32.bf16.bf16.f32 "
        "{%0,%1,%2,%3}, {%4,%5,%6,%7}, {%8,%9}, {%0,%1,%2,%3};"
        : "+f"(c[0]), "+f"(c[1]), "+f"(c[2]), "+f"(c[3])
        : "r"(a[0]), "r"(a[1]), "r"(a[2]), "r"(a[3]), "r"(b[0]), "r"(b[1]));
}

// ---------------------------------------------------------------------------
// bf16-split tensor-core GEMM (known-best config, unchanged from round 12):
//   C[M,N] = Ah@Bh^T + Ah@Bl^T + Al@Bh^T (+bias)
// Tile 128x128x32, 8 warps, cp.async double buffer, scalar-LDS fragments,
// single __syncthreads per K-chunk, fused attn-scalar epilogue,
// __launch_bounds__(256, 2) caps regs at 128 -> 2 blocks/SM.
// ---------------------------------------------------------------------------
#define PITCH      80                       // bytes per 32-bf16 row (40 halves)
#define TILE_B     (128 * PITCH)            // 10240 B
#define STAGE_B    (4 * TILE_B)             // 40960 B (Ah, Al, Bh, Bl)
#define GEMM_SMEM  (2 * STAGE_B)            // 81920 B

__global__ __launch_bounds__(256, 2)
void gemm_bf16_tc(const __nv_bfloat16* __restrict__ Ah,
                  const __nv_bfloat16* __restrict__ Al,
                  const __nv_bfloat16* __restrict__ Bh,
                  const __nv_bfloat16* __restrict__ Bl,
                  float* __restrict__ C, const float* __restrict__ bias,
                  const float* __restrict__ ws,   // att_src [HC] or null
                  const float* __restrict__ wd,   // att_dst [HC] or null
                  int M, int N, int K)
{
    extern __shared__ __align__(16) char smem[];
    const uint32_t sb = smem_u32(smem);
    const int tid  = threadIdx.x;
    const int wid  = tid >> 5, lane = tid & 31;
    const int wm   = wid >> 2, wn = wid & 3;      // warp grid 2x4
    const int g    = lane >> 2, q = lane & 3;
    const int m0   = blockIdx.y * 128, n0 = blockIdx.x * 128;
    const int KC   = K >> 5;

    auto load_chunk = [&](int kc, int st) {
        const int k0 = kc * 32;
        const uint32_t stb = sb + st * STAGE_B;
        #pragma unroll
        for (int t = 0; t < 4; t++) {
            const __nv_bfloat16* src =
                (t == 0) ? Ah : (t == 1) ? Al : (t == 2) ? Bh : Bl;
            const int  rbase = (t < 2) ? m0 : n0;
            const bool guard = (t < 2);
            const uint32_t tb = stb + t * TILE_B;
            #pragma unroll
            for (int i = 0; i < 2; i++) {
                int c   = tid + i * 256;          // 0..511 chunk id
                int row = c >> 2, cw = c & 3;     // 4 x 16B chunks per row
                int gr  = rbase + row;
                int ok  = (!guard || gr < M) ? 16 : 0;
                const __nv_bfloat16* s = src + (size_t)gr * K + k0 + cw * 8;
                cp_async16(tb + row * PITCH + cw * 16, s, ok);
            }
        }
    };

    float acc[4][4][4];
    #pragma unroll
    for (int i = 0; i < 4; i++)
        #pragma unroll
        for (int j = 0; j < 4; j++)
            #pragma unroll
            for (int r = 0; r < 4; r++) acc[i][j][r] = 0.f;

    load_chunk(0, 0);
    CP_ASYNC_COMMIT();

    for (int kc = 0; kc < KC; kc++) {
        CP_ASYNC_WAIT(0);        // chunk kc resident
        __syncthreads();         // publishes stage kc; proves compute(kc-1) done
        if (kc + 1 < KC) {
            load_chunk(kc + 1, (kc + 1) & 1);
            CP_ASYNC_COMMIT();
        }

        const uint32_t stb = sb + (kc & 1) * STAGE_B;
        const uint32_t sAh = stb;
        const uint32_t sAl = stb + TILE_B;
        const uint32_t sBh = stb + 2 * TILE_B;
        const uint32_t sBl = stb + 3 * TILE_B;

        #pragma unroll
        for (int kt = 0; kt < 2; kt++) {
            const uint32_t koff = kt * 32 + q * 4;  // bytes within row
            uint32_t ah[4][4], al[4][4], bh[4][2], bl[4][2];
            #pragma unroll
            for (int mt = 0; mt < 4; mt++) {
                uint32_t a0 = (uint32_t)((wm * 64 + mt * 16 + g) * PITCH) + koff;
                ah[mt][0] = lds32(sAh + a0);
                ah[mt][1] = lds32(sAh + a0 + 8 * PITCH);
                ah[mt][2] = lds32(sAh + a0 + 16);
                ah[mt][3] = lds32(sAh + a0 + 8 * PITCH + 16);
                al[mt][0] = lds32(sAl + a0);
                al[mt][1] = lds32(sAl + a0 + 8 * PITCH);
                al[mt][2] = lds32(sAl + a0 + 16);
                al[mt][3] = lds32(sAl + a0 + 8 * PITCH + 16);
            }
            #pragma unroll
            for (int nt = 0; nt < 4; nt++) {
                uint32_t b0 = (uint32_t)((wn * 32 + nt * 8 + g) * PITCH) + koff;
                bh[nt][0] = lds32(sBh + b0);
                bh[nt][1] = lds32(sBh + b0 + 16);
                bl[nt][0] = lds32(sBl + b0);
                bl[nt][1] = lds32(sBl + b0 + 16);
            }
            #pragma unroll
            for (int mt = 0; mt < 4; mt++)
                #pragma unroll
                for (int nt = 0; nt < 4; nt++) {
                    mma_bf16(acc[mt][nt], ah[mt], bh[nt]);
                    mma_bf16(acc[mt][nt], ah[mt], bl[nt]);
                    mma_bf16(acc[mt][nt], al[mt], bh[nt]);
                }
        }
    }

    // ---- store C (+ optional bias) ----
    #pragma unroll
    for (int mt = 0; mt < 4; mt++) {
        int r0 = m0 + wm * 64 + mt * 16 + g;
        #pragma unroll
        for (int nt = 0; nt < 4; nt++) {
            int cc = n0 + wn * 32 + nt * 8 + q * 2;
            float b0 = 0.f, b1 = 0.f;
            if (bias) { b0 = bias[cc]; b1 = bias[cc + 1]; }
            if (r0 < M) {
                float2 v = make_float2(acc[mt][nt][0] + b0, acc[mt][nt][1] + b1);
                *(float2*)(C + (size_t)r0 * N + cc) = v;
            }
            if (r0 + 8 < M) {
                float2 v = make_float2(acc[mt][nt][2] + b0, acc[mt][nt][3] + b1);
                *(float2*)(C + (size_t)(r0 + 8) * N + cc) = v;
            }
        }
    }

    // ---- fused attention scalars (GAT layers only) ----
    if (ws != nullptr) {
        __syncthreads();                        // done reading stages; reuse smem
        float* red = (float*)smem;              // [2][4][128] src/dst x wn x row
        float wsv[4][2], wdv[4][2];
        #pragma unroll
        for (int nt = 0; nt < 4; nt++) {
            int cc = n0 + wn * 32 + nt * 8 + q * 2;
            wsv[nt][0] = ws[cc];  wsv[nt][1] = ws[cc + 1];
            wdv[nt][0] = wd[cc];  wdv[nt][1] = wd[cc + 1];
        }
        #pragma unroll
        for (int mt = 0; mt < 4; mt++) {
            #pragma unroll
            for (int half = 0; half < 2; half++) {
                float ssrc = 0.f, sdst = 0.f;
                #pragma unroll
                for (int nt = 0; nt < 4; nt++) {
                    float v0 = acc[mt][nt][half * 2];
                    float v1 = acc[mt][nt][half * 2 + 1];
                    ssrc += v0 * wsv[nt][0] + v1 * wsv[nt][1];
                    sdst += v0 * wdv[nt][0] + v1 * wdv[nt][1];
                }
                ssrc += __shfl_xor_sync(0xffffffffu, ssrc, 1);
                ssrc += __shfl_xor_sync(0xffffffffu, ssrc, 2);
                sdst += __shfl_xor_sync(0xffffffffu, sdst, 1);
                sdst += __shfl_xor_sync(0xffffffffu, sdst, 2);
                if (q == 0) {
                    int rl = wm * 64 + mt * 16 + half * 8 + g;   // 0..127
                    red[(0 + wn) * 128 + rl] = ssrc;
                    red[(4 + wn) * 128 + rl] = sdst;
                }
            }
        }
        __syncthreads();
        int rl    = tid & 127;
        int which = tid >> 7;                   // 0 = src, 1 = dst
        const float* base = red + which * 4 * 128;
        float sum = base[0 * 128 + rl] + base[1 * 128 + rl]
                  + base[2 * 128 + rl] + base[3 * 128 + rl];
        int grow = m0 + rl;
        int head = n0 >> 7;                     // N-tile == head width
        if (grow < M) {
            float* dst = which ? g_adst : g_asrc;
            dst[grow * HEADS + head] = sum;
        }
    }
}

// ---------------------------------------------------------------------------
// Fused prep kernel 1: zero deg/cursor + all three weight transpose+splits.
// Block-range dispatch (all sections independent).  Grid = 224 blocks.
// ---------------------------------------------------------------------------
__device__ __forceinline__ void wt_split_body(
    const float* __restrict__ W, __nv_bfloat16* __restrict__ Th,
    __nv_bfloat16* __restrict__ Tl, int K, int N, int bsub, int nsub)
{
    int i      = bsub * blockDim.x + threadIdx.x;
    int stride = nsub * blockDim.x;
    int total  = K * N;
    for (int j = i; j < total; j += stride) {
        int n = j % N, k = j / N;
        float f = W[(size_t)k * N + n];
        __nv_bfloat16 h = __float2bfloat16_rn(f);
        Th[(size_t)n * K + k] = h;
        Tl[(size_t)n * K + k] = __float2bfloat16_rn(f - __bfloat162float(h));
    }
}

__global__ __launch_bounds__(256)
void prep_weights(const float* __restrict__ W1, const float* __restrict__ W2,
                  const float* __restrict__ Wfc)
{
    int b = blockIdx.x;                       // 0..223
    if (b < 32) {
        for (int i = b * 256 + threadIdx.x; i < NNODES; i += 32 * 256) {
            g_deg[i] = 0;
            g_cursor[i] = 0;
        }
    } else if (b < 96) {
        wt_split_body(W1, g_Wth1, g_Wtl1, IN_DIM, HC, b - 32, 64);
    } else if (b < 160) {
        wt_split_body(W2, g_Wth2, g_Wtl2, HC, HC, b - 96, 64);
    } else {
        wt_split_body(Wfc, g_Wthf, g_Wtlf, HC, OUT_DIM, b - 160, 64);
    }
}

// ---------------------------------------------------------------------------
// Fused prep kernel 2: bf16 split of x + CSR degree count.  Grid = 1024.
// ---------------------------------------------------------------------------
__global__ __launch_bounds__(256)
void prep_x_count(const float* __restrict__ x, const int* __restrict__ ei)
{
    int b = blockIdx.x;                       // 0..1023
    if (b < 768) {
        const long n4 = (long)NNODES * IN_DIM / 4;
        long i      = (long)b * 256 + threadIdx.x;
        long stride = 768L * 256;
        for (long j = i; j < n4; j += stride) {
            float4 f = ((const float4*)x)[j];
            __nv_bfloat16 h0 = __float2bfloat16_rn(f.x);
            __nv_bfloat16 h1 = __float2bfloat16_rn(f.y);
            __nv_bfloat16 h2 = __float2bfloat16_rn(f.z);
            __nv_bfloat16 h3 = __float2bfloat16_rn(f.w);
            ((__nv_bfloat162*)g_Ahi)[j * 2]     = __nv_bfloat162{h0, h1};
            ((__nv_bfloat162*)g_Ahi)[j * 2 + 1] = __nv_bfloat162{h2, h3};
            ((__nv_bfloat162*)g_Alo)[j * 2] = __nv_bfloat162{
                __float2bfloat16_rn(f.x - __bfloat162float(h0)),
                __float2bfloat16_rn(f.y - __bfloat162float(h1))};
            ((__nv_bfloat162*)g_Alo)[j * 2 + 1] = __nv_bfloat162{
                __float2bfloat16_rn(f.z - __bfloat162float(h2)),
                __float2bfloat16_rn(f.w - __bfloat162float(h3))};
        }
    } else {
        for (int idx = (b - 768) * 256 + threadIdx.x; idx < EPRIME;
             idx += 256 * 256) {
            int d = (idx < NEDGES) ? ei[NEDGES + idx] : idx - NEDGES;
            atomicAdd(&g_deg[d], 1);
        }
    }
}

// ---------------------------------------------------------------------------
// CSR scan: chunk-local scan (scan1), then merged sums-scan + apply (scan23).
// ---------------------------------------------------------------------------
__global__ void csr_scan1()
{
    __shared__ int s[256];
    int t = threadIdx.x, idx = blockIdx.x * 256 + t;
    int val = (idx < NNODES) ? g_deg[idx] : 0;
    s[t] = val;
    __syncthreads();
    #pragma unroll
    for (int off = 1; off < 256; off <<= 1) {
        int v = (t >= off) ? s[t - off] : 0;
        __syncthreads();
        s[t] += v;
        __syncthreads();
    }
    if (idx < NNODES) g_rowptr[idx] = s[t] - val;   // exclusive within chunk
    if (t == 255) g_bsums[blockIdx.x] = s[255];
}

// Each block redundantly scans the (<=256) chunk sums in smem, then applies
// its own exclusive offset to its rowptr chunk.  Replaces scan2 + scan3.
__global__ void csr_scan23(int nblk)
{
    __shared__ int s[256];
    int t = threadIdx.x;
    int val = (t < nblk) ? g_bsums[t] : 0;
    s[t] = val;
    __syncthreads();
    #pragma unroll
    for (int off = 1; off < 256; off <<= 1) {
        int v = (t >= off) ? s[t - off] : 0;
        __syncthreads();
        s[t] += v;
        __syncthreads();
    }
    int excl = s[blockIdx.x] - g_bsums[blockIdx.x]; // exclusive chunk offset
    int idx  = blockIdx.x * 256 + t;
    if (idx < NNODES) g_rowptr[idx] += excl;
}

__global__ void csr_scatter(const int* __restrict__ ei)
{
    int idx = blockIdx.x * blockDim.x + threadIdx.x;
    if (idx >= EPRIME) return;
    int s, d;
    if (idx < NEDGES) { s = ei[idx]; d = ei[NEDGES + idx]; }
    else              { s = d = idx - NEDGES; }
    int slot = g_rowptr[d] + atomicAdd(&g_cursor[d], 1);
    g_csrc[slot] = s;
}

// ---------------------------------------------------------------------------
// Fused GAT aggregation (unchanged from round 12): per-dst segment softmax +
// gather + bias + ReLU + bf16 hi/lo split.  One block (128 thr) per dst node;
// warp w = head w.  Register-cached fast path for deg <= 96.
// ---------------------------------------------------------------------------
#define AGG_CHUNK 64

__global__ __launch_bounds__(128)
void gat_aggregate(const float* __restrict__ h, const float* __restrict__ bias,
                   __nv_bfloat16* __restrict__ outHi,
                   __nv_bfloat16* __restrict__ outLo)
{
    __shared__ float s_alpha[HEADS][AGG_CHUNK];
    const int d    = blockIdx.x;
    const int tid  = threadIdx.x;
    const int head = tid >> 5, lane = tid & 31;
    const int beg  = g_rowptr[d];
    const int deg  = g_deg[d];
    const float adst = g_adst[d * HEADS + head];

    float4 acc = make_float4(0.f, 0.f, 0.f, 0.f);
    const float* hcol = h + tid * 4;               // column offset in row

    if (deg <= 96) {
        // ---- fast path: everything in registers, single gather pass ----
        int   se[3];
        float ve[3];
        #pragma unroll
        for (int c = 0; c < 3; c++) {
            int e = c * 32 + lane;
            if (e < deg) {
                int s = g_csrc[beg + e];
                float v = g_asrc[s * HEADS + head] + adst;
                ve[c] = v > 0.f ? v : NEG_SLOPE * v;
                se[c] = s;
            } else {
                se[c] = 0;
                ve[c] = -1e30f;
            }
        }
        float mx = fmaxf(ve[0], fmaxf(ve[1], ve[2]));
        #pragma unroll
        for (int o = 16; o > 0; o >>= 1)
            mx = fmaxf(mx, __shfl_xor_sync(0xffffffffu, mx, o));

        float ae[3];
        float sm = 0.f;
        #pragma unroll
        for (int c = 0; c < 3; c++) {
            float a = (c * 32 + lane < deg) ? __expf(ve[c] - mx) : 0.f;
            ae[c] = a;
            sm += a;
        }
        #pragma unroll
        for (int o = 16; o > 0; o >>= 1)
            sm += __shfl_xor_sync(0xffffffffu, sm, o);
        const float inv = 1.f / sm;

        #pragma unroll
        for (int c = 0; c < 3; c++) {
            int base = c * 32;
            if (base >= deg) break;
            int m = min(32, deg - base);
            int   sc = se[c];
            float ac = ae[c];
            #pragma unroll 4
            for (int l = 0; l < m; l++) {
                int   s = __shfl_sync(0xffffffffu, sc, l);
                float a = __shfl_sync(0xffffffffu, ac, l) * inv;
                float4 hv = *(const float4*)(hcol + (size_t)s * HC);
                acc.x += a * hv.x;
                acc.y += a * hv.y;
                acc.z += a * hv.z;
                acc.w += a * hv.w;
            }
        }
    } else {
        // ---- generic path (rare): 3-pass with smem alpha staging ----
        float mx = -1e30f;
        for (int e = lane; e < deg; e += 32) {
            int s = g_csrc[beg + e];
            float v = g_asrc[s * HEADS + head] + adst;
            v = v > 0.f ? v : NEG_SLOPE * v;
            mx = fmaxf(mx, v);
        }
        #pragma unroll
        for (int o = 16; o > 0; o >>= 1)
            mx = fmaxf(mx, __shfl_xor_sync(0xffffffffu, mx, o));

        float sm = 0.f;
        for (int e = lane; e < deg; e += 32) {
            int s = g_csrc[beg + e];
            float v = g_asrc[s * HEADS + head] + adst;
            v = v > 0.f ? v : NEG_SLOPE * v;
            sm += __expf(v - mx);
        }
        #pragma unroll
        for (int o = 16; o > 0; o >>= 1)
            sm += __shfl_xor_sync(0xffffffffu, sm, o);
        const float inv = 1.f / sm;

        for (int base = 0; base < deg; base += AGG_CHUNK) {
            int m = min(AGG_CHUNK, deg - base);
            for (int e = lane; e < m; e += 32) {
                int s = g_csrc[beg + base + e];
                float v = g_asrc[s * HEADS + head] + adst;
                v = v > 0.f ? v : NEG_SLOPE * v;
                s_alpha[head][e] = __expf(v - mx) * inv;
            }
            __syncwarp();
            #pragma unroll 4
            for (int e = 0; e < m; e++) {
                int s = g_csrc[beg + base + e];
                float a = s_alpha[head][e];
                float4 hv = *(const float4*)(hcol + (size_t)s * HC);
                acc.x += a * hv.x;
                acc.y += a * hv.y;
                acc.z += a * hv.z;
                acc.w += a * hv.w;
            }
            __syncwarp();
        }
    }

    // epilogue: bias + relu + bf16 split
    const float4 bv = *(const float4*)(bias + tid * 4);
    float o0 = fmaxf(acc.x + bv.x, 0.f);
    float o1 = fmaxf(acc.y + bv.y, 0.f);
    float o2 = fmaxf(acc.z + bv.z, 0.f);
    float o3 = fmaxf(acc.w + bv.w, 0.f);
    __nv_bfloat16 h0 = __float2bfloat16_rn(o0);
    __nv_bfloat16 h1 = __float2bfloat16_rn(o1);
    __nv_bfloat16 h2 = __float2bfloat16_rn(o2);
    __nv_bfloat16 h3 = __float2bfloat16_rn(o3);
    __nv_bfloat162* dh = (__nv_bfloat162*)(outHi + (size_t)d * HC + tid * 4);
    __nv_bfloat162* dl = (__nv_bfloat162*)(outLo + (size_t)d * HC + tid * 4);
    dh[0] = __nv_bfloat162{h0, h1};
    dh[1] = __nv_bfloat162{h2, h3};
    dl[0] = __nv_bfloat162{__float2bfloat16_rn(o0 - __bfloat162float(h0)),
                           __float2bfloat16_rn(o1 - __bfloat162float(h1))};
    dl[1] = __nv_bfloat162{__float2bfloat16_rn(o2 - __bfloat162float(h2)),
                           __float2bfloat16_rn(o3 - __bfloat162float(h3))};
}

// ---------------------------------------------------------------------------
// Host-side launch
// ---------------------------------------------------------------------------
extern "C" void kernel_launch(void* const* d_in, const int* in_sizes, int n_in,
                              void* d_out, int out_size)
{
    const float* x      = (const float*)d_in[0];
    const int*   ei     = (const int*)  d_in[1];
    const float* W1     = (const float*)d_in[2];
    const float* a1_src = (const float*)d_in[3];
    const float* a1_dst = (const float*)d_in[4];
    const float* b1     = (const float*)d_in[5];
    const float* W2     = (const float*)d_in[6];
    const float* a2_src = (const float*)d_in[7];
    const float* a2_dst = (const float*)d_in[8];
    const float* b2     = (const float*)d_in[9];
    const float* Wfc    = (const float*)d_in[10];
    const float* bfc    = (const float*)d_in[11];
    float* out = (float*)d_out;

    float* bufA;
    __nv_bfloat16 *Ahi, *Alo, *Wth1, *Wtl1, *Wth2, *Wtl2, *Wthf, *Wtlf;
    cudaGetSymbolAddress((void**)&bufA, g_bufA);
    cudaGetSymbolAddress((void**)&Ahi,  g_Ahi);
    cudaGetSymbolAddress((void**)&Alo,  g_Alo);
    cudaGetSymbolAddress((void**)&Wth1, g_Wth1);
    cudaGetSymbolAddress((void**)&Wtl1, g_Wtl1);
    cudaGetSymbolAddress((void**)&Wth2, g_Wth2);
    cudaGetSymbolAddress((void**)&Wtl2, g_Wtl2);
    cudaGetSymbolAddress((void**)&Wthf, g_Wthf);
    cudaGetSymbolAddress((void**)&Wtlf, g_Wtlf);

    cudaFuncSetAttribute(gemm_bf16_tc,
                         cudaFuncAttributeMaxDynamicSharedMemorySize, GEMM_SMEM);

    const int MB    = (NNODES + 127) / 128;       // 391
    const int eb    = (EPRIME + 255) / 256;
    const int nblk  = (NNODES + 255) / 256;       // 196 (scan chunks)

    // 1. zero deg/cursor + all weight splits (independent sections)
    prep_weights<<<224, 256>>>(W1, W2, Wfc);
    // 2. x bf16 split + CSR degree count (independent sections)
    prep_x_count<<<1024, 256>>>(x, ei);
    // 3. chunk-local rowptr scan
    csr_scan1<<<nblk, 256>>>();
    // 4. layer-1 GEMM (profiling slot)
    gemm_bf16_tc<<<dim3(HC / 128, MB), 256, GEMM_SMEM>>>(
        Ahi, Alo, Wth1, Wtl1, bufA, nullptr, a1_src, a1_dst, NNODES, HC, IN_DIM);
    // 5. merged sums-scan + apply
    csr_scan23<<<nblk, 256>>>(nblk);
    // 6. CSR scatter
    csr_scatter<<<eb, 256>>>(ei);
    // 7. layer-1 aggregate (softmax + gather + bias + relu + split)
    gat_aggregate<<<NNODES, 128>>>(bufA, b1, Ahi, Alo);

    // 8-9. layer 2
    gemm_bf16_tc<<<dim3(HC / 128, MB), 256, GEMM_SMEM>>>(
        Ahi, Alo, Wth2, Wtl2, bufA, nullptr, a2_src, a2_dst, NNODES, HC, HC);
    gat_aggregate<<<NNODES, 128>>>(bufA, b2, Ahi, Alo);

    // 10. FC head
    gemm_bf16_tc<<<dim3(OUT_DIM / 128, MB), 256, GEMM_SMEM>>>(
        Ahi, Alo, Wthf, Wtlf, out, bfc, nullptr, nullptr, NNODES, OUT_DIM, HC);
}

// round 14
// speedup vs baseline: 1.2749x; 1.1302x over previous
#include <cuda_runtime.h>
#include <cuda_bf16.h>
#include <cstdint>

// Problem constants (fixed by the dataset)
#define NNODES   50000
#define NEDGES   500000
#define IN_DIM   384
#define HID      128
#define HEADS    4
#define HC       (HEADS * HID)     // 512
#define OUT_DIM  384
#define NEG_SLOPE 0.2f
#define EPRIME   (NEDGES + NNODES) // edges + self loops

// ---------------------------------------------------------------------------
// Scratch (static device globals; allocation inside kernel_launch is banned)
// ---------------------------------------------------------------------------
__device__ float g_bufA[(size_t)NNODES * HC];                // GEMM output h
__device__ __align__(16) __nv_bfloat16 g_Ahi[(size_t)NNODES * HC];
__device__ __align__(16) __nv_bfloat16 g_Alo[(size_t)NNODES * HC];
// per-layer transposed weights (hi/lo)
__device__ __align__(16) __nv_bfloat16 g_Wth1[HC * IN_DIM];
__device__ __align__(16) __nv_bfloat16 g_Wtl1[HC * IN_DIM];
__device__ __align__(16) __nv_bfloat16 g_Wth2[HC * HC];
__device__ __align__(16) __nv_bfloat16 g_Wtl2[HC * HC];
__device__ __align__(16) __nv_bfloat16 g_Wthf[OUT_DIM * HC];
__device__ __align__(16) __nv_bfloat16 g_Wtlf[OUT_DIM * HC];
__device__ float g_asrc[NNODES * HEADS];
__device__ float g_adst[NNODES * HEADS];
// CSR (by dst) of the self-loop-augmented graph
__device__ int g_deg[NNODES];
__device__ int g_rowptr[NNODES];
__device__ int g_cursor[NNODES];
__device__ int g_csrc[EPRIME];
__device__ int g_bsums[256];

// ---------------------------------------------------------------------------
// Small PTX helpers (generic sm_80+ subset only — the bench's PTX stage is
// compute_103 (no 'a'), so no tcgen05/TMA instructions may appear here.)
// ---------------------------------------------------------------------------
__device__ __forceinline__ uint32_t smem_u32(const void* p) {
    uint32_t a;
    asm("{ .reg .u64 t; cvta.to.shared.u64 t, %1; cvt.u32.u64 %0, t; }"
        : "=r"(a) : "l"(p));
    return a;
}

__device__ __forceinline__ void cp_async16(uint32_t dst, const void* src, int srcBytes) {
    asm volatile("cp.async.cg.shared.global [%0], [%1], 16, %2;"
                 :: "r"(dst), "l"(src), "r"(srcBytes));
}
#define CP_ASYNC_COMMIT() asm volatile("cp.async.commit_group;" ::: "memory")
#define CP_ASYNC_WAIT(n)  asm volatile("cp.async.wait_group %0;" :: "n"(n) : "memory")

__device__ __forceinline__ void ldsm_x4(uint32_t* r, uint32_t addr) {
    asm volatile("ldmatrix.sync.aligned.m8n8.x4.shared.b16 {%0,%1,%2,%3}, [%4];"
                 : "=r"(r[0]), "=r"(r[1]), "=r"(r[2]), "=r"(r[3]) : "r"(addr));
}
__device__ __forceinline__ void ldsm_x2(uint32_t* r, uint32_t addr) {
    asm volatile("ldmatrix.sync.aligned.m8n8.x2.shared.b16 {%0,%1}, [%2];"
                 : "=r"(r[0]), "=r"(r[1]) : "r"(addr));
}

__device__ __forceinline__ void mma_bf16(float* c, const uint32_t* a, const uint32_t* b) {
    asm volatile(
        "mma.sync.aligned.m16n8k16.row.col.f32.bf16.bf16.f32 "
        "{%0,%1,%2,%3}, {%4,%5,%6,%7}, {%8,%9}, {%0,%1,%2,%3};"
        : "+f"(c[0]), "+f"(c[1]), "+f"(c[2]), "+f"(c[3])
        : "r"(a[0]), "r"(a[1]), "r"(a[2]), "r"(a[3]), "r"(b[0]), "r"(b[1]));
}

// ---------------------------------------------------------------------------
// bf16-split tensor-core GEMM:
//   C[M,N] = Ah@Bh^T + Ah@Bl^T + Al@Bh^T (+bias)
// Tile 128x128x32, 8 warps (warp tile 64x32), cp.async double buffer,
// single __syncthreads per K-chunk, fused attn-scalar epilogue,
// __launch_bounds__(256, 2) -> 2 blocks/SM.
// Round-14: PITCH=64 (zero pad) + per-row XOR chunk swizzle
//   chunk' = chunk ^ ((row>>1)&3)
// which makes BOTH the cp.async 16B stores and the ldmatrix row-pointer
// phases hit 8 distinct bank-quads (the PITCH-80/48 patterns had period-8
// bank aliasing between rows 0-7 and 8-15 -> the earlier ldmatrix losses).
// Fragment loads: ldmatrix x4 (A) / x2 (B): 16 LDSM vs 48 scalar LDS per kt.
// ---------------------------------------------------------------------------
#define PITCH      64                       // bytes per 32-bf16 row (no pad)
#define TILE_B     (128 * PITCH)            // 8192 B
#define STAGE_B    (4 * TILE_B)             // 32768 B (Ah, Al, Bh, Bl)
#define GEMM_SMEM  (2 * STAGE_B)            // 65536 B

__global__ __launch_bounds__(256, 2)
void gemm_bf16_tc(const __nv_bfloat16* __restrict__ Ah,
                  const __nv_bfloat16* __restrict__ Al,
                  const __nv_bfloat16* __restrict__ Bh,
                  const __nv_bfloat16* __restrict__ Bl,
                  float* __restrict__ C, const float* __restrict__ bias,
                  const float* __restrict__ ws,   // att_src [HC] or null
                  const float* __restrict__ wd,   // att_dst [HC] or null
                  int M, int N, int K)
{
    extern __shared__ __align__(16) char smem[];
    const uint32_t sb = smem_u32(smem);
    const int tid  = threadIdx.x;
    const int wid  = tid >> 5, lane = tid & 31;
    const int wm   = wid >> 2, wn = wid & 3;      // warp grid 2x4
    const int g    = lane >> 2, q = lane & 3;
    const int m0   = blockIdx.y * 128, n0 = blockIdx.x * 128;
    const int KC   = K >> 5;

    // ldmatrix per-lane offsets (swizzled); invariant under mt/nt row bases
    const int arow   = lane & 15;
    const int achunk = lane >> 4;                 // 0/1
    const uint32_t aoff =
        (uint32_t)(arow * PITCH + ((achunk ^ ((arow >> 1) & 3)) << 4));
    const int brow   = lane & 7;
    const int bchunk = (lane >> 3) & 1;
    const uint32_t boff =
        (uint32_t)(brow * PITCH + ((bchunk ^ ((brow >> 1) & 3)) << 4));

    // async tile loader: 4 tiles of [128 x 32bf16], swizzled 16B stores
    auto load_chunk = [&](int kc, int st) {
        const int k0 = kc * 32;
        const uint32_t stb = sb + st * STAGE_B;
        #pragma unroll
        for (int t = 0; t < 4; t++) {
            const __nv_bfloat16* src =
                (t == 0) ? Ah : (t == 1) ? Al : (t == 2) ? Bh : Bl;
            const int  rbase = (t < 2) ? m0 : n0;
            const bool guard = (t < 2);
            const uint32_t tb = stb + t * TILE_B;
            #pragma unroll
            for (int i = 0; i < 2; i++) {
                int c16 = tid + i * 256;          // 0..511 chunk id
                int row = c16 >> 2, cw = c16 & 3; // 4 x 16B chunks per row
                int gr  = rbase + row;
                int ok  = (!guard || gr < M) ? 16 : 0;
                const __nv_bfloat16* s = src + (size_t)gr * K + k0 + cw * 8;
                uint32_t dst = tb + (uint32_t)(row * PITCH)
                             + (uint32_t)(((cw ^ ((row >> 1) & 3)) << 4));
                cp_async16(dst, s, ok);
            }
        }
    };

    float acc[4][4][4];
    #pragma unroll
    for (int i = 0; i < 4; i++)
        #pragma unroll
        for (int j = 0; j < 4; j++)
            #pragma unroll
            for (int r = 0; r < 4; r++) acc[i][j][r] = 0.f;

    load_chunk(0, 0);
    CP_ASYNC_COMMIT();

    for (int kc = 0; kc < KC; kc++) {
        CP_ASYNC_WAIT(0);        // chunk kc resident
        __syncthreads();         // publishes stage kc; proves compute(kc-1) done
        if (kc + 1 < KC) {
            load_chunk(kc + 1, (kc + 1) & 1);
            CP_ASYNC_COMMIT();
        }

        const uint32_t stb = sb + (kc & 1) * STAGE_B;
        const uint32_t sAh = stb;
        const uint32_t sAl = stb + TILE_B;
        const uint32_t sBh = stb + 2 * TILE_B;
        const uint32_t sBl = stb + 3 * TILE_B;

        #pragma unroll
        for (int kt = 0; kt < 2; kt++) {
            const uint32_t ktx = (uint32_t)(kt << 5);   // XOR bit 5: chunks +2
            // B fragments for all 4 n-tiles (resident)
            uint32_t bh[4][2], bl[4][2];
            #pragma unroll
            for (int nt = 0; nt < 4; nt++) {
                uint32_t nb = (uint32_t)((wn * 32 + nt * 8) * PITCH);
                ldsm_x2(bh[nt], sBh + nb + (boff ^ ktx));
                ldsm_x2(bl[nt], sBl + nb + (boff ^ ktx));
            }
            #pragma unroll
            for (int mt = 0; mt < 4; mt++) {
                uint32_t mb = (uint32_t)((wm * 64 + mt * 16) * PITCH);
                uint32_t ah[4], al[4];
                ldsm_x4(ah, sAh + mb + (aoff ^ ktx));
                ldsm_x4(al, sAl + mb + (aoff ^ ktx));
                #pragma unroll
                for (int nt = 0; nt < 4; nt++) {
                    mma_bf16(acc[mt][nt], ah, bh[nt]);
                    mma_bf16(acc[mt][nt], ah, bl[nt]);
                    mma_bf16(acc[mt][nt], al, bh[nt]);
                }
            }
        }
    }

    // ---- store C (+ optional bias) ----
    #pragma unroll
    for (int mt = 0; mt < 4; mt++) {
        int r0 = m0 + wm * 64 + mt * 16 + g;
        #pragma unroll
        for (int nt = 0; nt < 4; nt++) {
            int cc = n0 + wn * 32 + nt * 8 + q * 2;
            float b0 = 0.f, b1 = 0.f;
            if (bias) { b0 = bias[cc]; b1 = bias[cc + 1]; }
            if (r0 < M) {
                float2 v = make_float2(acc[mt][nt][0] + b0, acc[mt][nt][1] + b1);
                *(float2*)(C + (size_t)r0 * N + cc) = v;
            }
            if (r0 + 8 < M) {
                float2 v = make_float2(acc[mt][nt][2] + b0, acc[mt][nt][3] + b1);
                *(float2*)(C + (size_t)(r0 + 8) * N + cc) = v;
            }
        }
    }

    // ---- fused attention scalars (GAT layers only) ----
    if (ws != nullptr) {
        __syncthreads();                        // done reading stages; reuse smem
        float* red = (float*)smem;              // [2][4][128] src/dst x wn x row
        float wsv[4][2], wdv[4][2];
        #pragma unroll
        for (int nt = 0; nt < 4; nt++) {
            int cc = n0 + wn * 32 + nt * 8 + q * 2;
            wsv[nt][0] = ws[cc];  wsv[nt][1] = ws[cc + 1];
            wdv[nt][0] = wd[cc];  wdv[nt][1] = wd[cc + 1];
        }
        #pragma unroll
        for (int mt = 0; mt < 4; mt++) {
            #pragma unroll
            for (int half = 0; half < 2; half++) {
                float ssrc = 0.f, sdst = 0.f;
                #pragma unroll
                for (int nt = 0; nt < 4; nt++) {
                    float v0 = acc[mt][nt][half * 2];
                    float v1 = acc[mt][nt][half * 2 + 1];
                    ssrc += v0 * wsv[nt][0] + v1 * wsv[nt][1];
                    sdst += v0 * wdv[nt][0] + v1 * wdv[nt][1];
                }
                ssrc += __shfl_xor_sync(0xffffffffu, ssrc, 1);
                ssrc += __shfl_xor_sync(0xffffffffu, ssrc, 2);
                sdst += __shfl_xor_sync(0xffffffffu, sdst, 1);
                sdst += __shfl_xor_sync(0xffffffffu, sdst, 2);
                if (q == 0) {
                    int rl = wm * 64 + mt * 16 + half * 8 + g;   // 0..127
                    red[(0 + wn) * 128 + rl] = ssrc;
                    red[(4 + wn) * 128 + rl] = sdst;
                }
            }
        }
        __syncthreads();
        int rl    = tid & 127;
        int which = tid >> 7;                   // 0 = src, 1 = dst
        const float* base = red + which * 4 * 128;
        float sum = base[0 * 128 + rl] + base[1 * 128 + rl]
                  + base[2 * 128 + rl] + base[3 * 128 + rl];
        int grow = m0 + rl;
        int head = n0 >> 7;                     // N-tile == head width
        if (grow < M) {
            float* dst = which ? g_adst : g_asrc;
            dst[grow * HEADS + head] = sum;
        }
    }
}

// ---------------------------------------------------------------------------
// Fused prep kernel 1: zero deg/cursor + all three weight transpose+splits.
// ---------------------------------------------------------------------------
__device__ __forceinline__ void wt_split_body(
    const float* __restrict__ W, __nv_bfloat16* __restrict__ Th,
    __nv_bfloat16* __restrict__ Tl, int K, int N, int bsub, int nsub)
{
    int i      = bsub * blockDim.x + threadIdx.x;
    int stride = nsub * blockDim.x;
    int total  = K * N;
    for (int j = i; j < total; j += stride) {
        int n = j % N, k = j / N;
        float f = W[(size_t)k * N + n];
        __nv_bfloat16 h = __float2bfloat16_rn(f);
        Th[(size_t)n * K + k] = h;
        Tl[(size_t)n * K + k] = __float2bfloat16_rn(f - __bfloat162float(h));
    }
}

__global__ __launch_bounds__(256)
void prep_weights(const float* __restrict__ W1, const float* __restrict__ W2,
                  const float* __restrict__ Wfc)
{
    int b = blockIdx.x;                       // 0..223
    if (b < 32) {
        for (int i = b * 256 + threadIdx.x; i < NNODES; i += 32 * 256) {
            g_deg[i] = 0;
            g_cursor[i] = 0;
        }
    } else if (b < 96) {
        wt_split_body(W1, g_Wth1, g_Wtl1, IN_DIM, HC, b - 32, 64);
    } else if (b < 160) {
        wt_split_body(W2, g_Wth2, g_Wtl2, HC, HC, b - 96, 64);
    } else {
        wt_split_body(Wfc, g_Wthf, g_Wtlf, HC, OUT_DIM, b - 160, 64);
    }
}

// ---------------------------------------------------------------------------
// Fused prep kernel 2: bf16 split of x + CSR degree count.  Grid = 1024.
// ---------------------------------------------------------------------------
__global__ __launch_bounds__(256)
void prep_x_count(const float* __restrict__ x, const int* __restrict__ ei)
{
    int b = blockIdx.x;                       // 0..1023
    if (b < 768) {
        const long n4 = (long)NNODES * IN_DIM / 4;
        long i      = (long)b * 256 + threadIdx.x;
        long stride = 768L * 256;
        for (long j = i; j < n4; j += stride) {
            float4 f = ((const float4*)x)[j];
            __nv_bfloat16 h0 = __float2bfloat16_rn(f.x);
            __nv_bfloat16 h1 = __float2bfloat16_rn(f.y);
            __nv_bfloat16 h2 = __float2bfloat16_rn(f.z);
            __nv_bfloat16 h3 = __float2bfloat16_rn(f.w);
            ((__nv_bfloat162*)g_Ahi)[j * 2]     = __nv_bfloat162{h0, h1};
            ((__nv_bfloat162*)g_Ahi)[j * 2 + 1] = __nv_bfloat162{h2, h3};
            ((__nv_bfloat162*)g_Alo)[j * 2] = __nv_bfloat162{
                __float2bfloat16_rn(f.x - __bfloat162float(h0)),
                __float2bfloat16_rn(f.y - __bfloat162float(h1))};
            ((__nv_bfloat162*)g_Alo)[j * 2 + 1] = __nv_bfloat162{
                __float2bfloat16_rn(f.z - __bfloat162float(h2)),
                __float2bfloat16_rn(f.w - __bfloat162float(h3))};
        }
    } else {
        for (int idx = (b - 768) * 256 + threadIdx.x; idx < EPRIME;
             idx += 256 * 256) {
            int d = (idx < NEDGES) ? ei[NEDGES + idx] : idx - NEDGES;
            atomicAdd(&g_deg[d], 1);
        }
    }
}

// ---------------------------------------------------------------------------
// CSR scan: chunk-local scan (scan1), then merged sums-scan + apply (scan23).
// ---------------------------------------------------------------------------
__global__ void csr_scan1()
{
    __shared__ int s[256];
    int t = threadIdx.x, idx = blockIdx.x * 256 + t;
    int val = (idx < NNODES) ? g_deg[idx] : 0;
    s[t] = val;
    __syncthreads();
    #pragma unroll
    for (int off = 1; off < 256; off <<= 1) {
        int v = (t >= off) ? s[t - off] : 0;
        __syncthreads();
        s[t] += v;
        __syncthreads();
    }
    if (idx < NNODES) g_rowptr[idx] = s[t] - val;   // exclusive within chunk
    if (t == 255) g_bsums[blockIdx.x] = s[255];
}

__global__ void csr_scan23(int nblk)
{
    __shared__ int s[256];
    int t = threadIdx.x;
    int val = (t < nblk) ? g_bsums[t] : 0;
    s[t] = val;
    __syncthreads();
    #pragma unroll
    for (int off = 1; off < 256; off <<= 1) {
        int v = (t >= off) ? s[t - off] : 0;
        __syncthreads();
        s[t] += v;
        __syncthreads();
    }
    int excl = s[blockIdx.x] - g_bsums[blockIdx.x]; // exclusive chunk offset
    int idx  = blockIdx.x * 256 + t;
    if (idx < NNODES) g_rowptr[idx] += excl;
}

__global__ void csr_scatter(const int* __restrict__ ei)
{
    int idx = blockIdx.x * blockDim.x + threadIdx.x;
    if (idx >= EPRIME) return;
    int s, d;
    if (idx < NEDGES) { s = ei[idx]; d = ei[NEDGES + idx]; }
    else              { s = d = idx - NEDGES; }
    int slot = g_rowptr[d] + atomicAdd(&g_cursor[d], 1);
    g_csrc[slot] = s;
}

// ---------------------------------------------------------------------------
// Fused GAT aggregation (unchanged): per-dst segment softmax + gather +
// bias + ReLU + bf16 hi/lo split.  One block (128 thr) per dst node;
// warp w = head w.  Register-cached fast path for deg <= 96.
// ---------------------------------------------------------------------------
#define AGG_CHUNK 64

__global__ __launch_bounds__(128)
void gat_aggregate(const float* __restrict__ h, const float* __restrict__ bias,
                   __nv_bfloat16* __restrict__ outHi,
                   __nv_bfloat16* __restrict__ outLo)
{
    __shared__ float s_alpha[HEADS][AGG_CHUNK];
    const int d    = blockIdx.x;
    const int tid  = threadIdx.x;
    const int head = tid >> 5, lane = tid & 31;
    const int beg  = g_rowptr[d];
    const int deg  = g_deg[d];
    const float adst = g_adst[d * HEADS + head];

    float4 acc = make_float4(0.f, 0.f, 0.f, 0.f);
    const float* hcol = h + tid * 4;               // column offset in row

    if (deg <= 96) {
        // ---- fast path: everything in registers, single gather pass ----
        int   se[3];
        float ve[3];
        #pragma unroll
        for (int c = 0; c < 3; c++) {
            int e = c * 32 + lane;
            if (e < deg) {
                int s = g_csrc[beg + e];
                float v = g_asrc[s * HEADS + head] + adst;
                ve[c] = v > 0.f ? v : NEG_SLOPE * v;
                se[c] = s;
            } else {
                se[c] = 0;
                ve[c] = -1e30f;
            }
        }
        float mx = fmaxf(ve[0], fmaxf(ve[1], ve[2]));
        #pragma unroll
        for (int o = 16; o > 0; o >>= 1)
            mx = fmaxf(mx, __shfl_xor_sync(0xffffffffu, mx, o));

        float ae[3];
        float sm = 0.f;
        #pragma unroll
        for (int c = 0; c < 3; c++) {
            float a = (c * 32 + lane < deg) ? __expf(ve[c] - mx) : 0.f;
            ae[c] = a;
            sm += a;
        }
        #pragma unroll
        for (int o = 16; o > 0; o >>= 1)
            sm += __shfl_xor_sync(0xffffffffu, sm, o);
        const float inv = 1.f / sm;

        #pragma unroll
        for (int c = 0; c < 3; c++) {
            int base = c * 32;
            if (base >= deg) break;
            int m = min(32, deg - base);
            int   sc = se[c];
            float ac = ae[c];
            #pragma unroll 4
            for (int l = 0; l < m; l++) {
                int   s = __shfl_sync(0xffffffffu, sc, l);
                float a = __shfl_sync(0xffffffffu, ac, l) * inv;
                float4 hv = *(const float4*)(hcol + (size_t)s * HC);
                acc.x += a * hv.x;
                acc.y += a * hv.y;
                acc.z += a * hv.z;
                acc.w += a * hv.w;
            }
        }
    } else {
        // ---- generic path (rare): 3-pass with smem alpha staging ----
        float mx = -1e30f;
        for (int e = lane; e < deg; e += 32) {
            int s = g_csrc[beg + e];
            float v = g_asrc[s * HEADS + head] + adst;
            v = v > 0.f ? v : NEG_SLOPE * v;
            mx = fmaxf(mx, v);
        }
        #pragma unroll
        for (int o = 16; o > 0; o >>= 1)
            mx = fmaxf(mx, __shfl_xor_sync(0xffffffffu, mx, o));

        float sm = 0.f;
        for (int e = lane; e < deg; e += 32) {
            int s = g_csrc[beg + e];
            float v = g_asrc[s * HEADS + head] + adst;
            v = v > 0.f ? v : NEG_SLOPE * v;
            sm += __expf(v - mx);
        }
        #pragma unroll
        for (int o = 16; o > 0; o >>= 1)
            sm += __shfl_xor_sync(0xffffffffu, sm, o);
        const float inv = 1.f / sm;

        for (int base = 0; base < deg; base += AGG_CHUNK) {
            int m = min(AGG_CHUNK, deg - base);
            for (int e = lane; e < m; e += 32) {
                int s = g_csrc[beg + base + e];
                float v = g_asrc[s * HEADS + head] + adst;
                v = v > 0.f ? v : NEG_SLOPE * v;
                s_alpha[head][e] = __expf(v - mx) * inv;
            }
            __syncwarp();
            #pragma unroll 4
            for (int e = 0; e < m; e++) {
                int s = g_csrc[beg + base + e];
                float a = s_alpha[head][e];
                float4 hv = *(const float4*)(hcol + (size_t)s * HC);
                acc.x += a * hv.x;
                acc.y += a * hv.y;
                acc.z += a * hv.z;
                acc.w += a * hv.w;
            }
            __syncwarp();
        }
    }

    // epilogue: bias + relu + bf16 split
    const float4 bv = *(const float4*)(bias + tid * 4);
    float o0 = fmaxf(acc.x + bv.x, 0.f);
    float o1 = fmaxf(acc.y + bv.y, 0.f);
    float o2 = fmaxf(acc.z + bv.z, 0.f);
    float o3 = fmaxf(acc.w + bv.w, 0.f);
    __nv_bfloat16 h0 = __float2bfloat16_rn(o0);
    __nv_bfloat16 h1 = __float2bfloat16_rn(o1);
    __nv_bfloat16 h2 = __float2bfloat16_rn(o2);
    __nv_bfloat16 h3 = __float2bfloat16_rn(o3);
    __nv_bfloat162* dh = (__nv_bfloat162*)(outHi + (size_t)d * HC + tid * 4);
    __nv_bfloat162* dl = (__nv_bfloat162*)(outLo + (size_t)d * HC + tid * 4);
    dh[0] = __nv_bfloat162{h0, h1};
    dh[1] = __nv_bfloat162{h2, h3};
    dl[0] = __nv_bfloat162{__float2bfloat16_rn(o0 - __bfloat162float(h0)),
                           __float2bfloat16_rn(o1 - __bfloat162float(h1))};
    dl[1] = __nv_bfloat162{__float2bfloat16_rn(o2 - __bfloat162float(h2)),
                           __float2bfloat16_rn(o3 - __bfloat162float(h3))};
}

// ---------------------------------------------------------------------------
// Host-side launch
// ---------------------------------------------------------------------------
extern "C" void kernel_launch(void* const* d_in, const int* in_sizes, int n_in,
                              void* d_out, int out_size)
{
    const float* x      = (const float*)d_in[0];
    const int*   ei     = (const int*)  d_in[1];
    const float* W1     = (const float*)d_in[2];
    const float* a1_src = (const float*)d_in[3];
    const float* a1_dst = (const float*)d_in[4];
    const float* b1     = (const float*)d_in[5];
    const float* W2     = (const float*)d_in[6];
    const float* a2_src = (const float*)d_in[7];
    const float* a2_dst = (const float*)d_in[8];
    const float* b2     = (const float*)d_in[9];
    const float* Wfc    = (const float*)d_in[10];
    const float* bfc    = (const float*)d_in[11];
    float* out = (float*)d_out;

    float* bufA;
    __nv_bfloat16 *Ahi, *Alo, *Wth1, *Wtl1, *Wth2, *Wtl2, *Wthf, *Wtlf;
    cudaGetSymbolAddress((void**)&bufA, g_bufA);
    cudaGetSymbolAddress((void**)&Ahi,  g_Ahi);
    cudaGetSymbolAddress((void**)&Alo,  g_Alo);
    cudaGetSymbolAddress((void**)&Wth1, g_Wth1);
    cudaGetSymbolAddress((void**)&Wtl1, g_Wtl1);
    cudaGetSymbolAddress((void**)&Wth2, g_Wth2);
    cudaGetSymbolAddress((void**)&Wtl2, g_Wtl2);
    cudaGetSymbolAddress((void**)&Wthf, g_Wthf);
    cudaGetSymbolAddress((void**)&Wtlf, g_Wtlf);

    cudaFuncSetAttribute(gemm_bf16_tc,
                         cudaFuncAttributeMaxDynamicSharedMemorySize, GEMM_SMEM);

    const int MB    = (NNODES + 127) / 128;       // 391
    const int eb    = (EPRIME + 255) / 256;
    const int nblk  = (NNODES + 255) / 256;       // 196 (scan chunks)

    // 1. zero deg/cursor + all weight splits (independent sections)
    prep_weights<<<224, 256>>>(W1, W2, Wfc);
    // 2. x bf16 split + CSR degree count (independent sections)
    prep_x_count<<<1024, 256>>>(x, ei);
    // 3. chunk-local rowptr scan
    csr_scan1<<<nblk, 256>>>();
    // 4. layer-1 GEMM (profiling slot)
    gemm_bf16_tc<<<dim3(HC / 128, MB), 256, GEMM_SMEM>>>(
        Ahi, Alo, Wth1, Wtl1, bufA, nullptr, a1_src, a1_dst, NNODES, HC, IN_DIM);
    // 5. merged sums-scan + apply
    csr_scan23<<<nblk, 256>>>(nblk);
    // 6. CSR scatter
    csr_scatter<<<eb, 256>>>(ei);
    // 7. layer-1 aggregate (softmax + gather + bias + relu + split)
    gat_aggregate<<<NNODES, 128>>>(bufA, b1, Ahi, Alo);

    // 8-9. layer 2
    gemm_bf16_tc<<<dim3(HC / 128, MB), 256, GEMM_SMEM>>>(
        Ahi, Alo, Wth2, Wtl2, bufA, nullptr, a2_src, a2_dst, NNODES, HC, HC);
    gat_aggregate<<<NNODES, 128>>>(bufA, b2, Ahi, Alo);

    // 10. FC head
    gemm_bf16_tc<<<dim3(OUT_DIM / 128, MB), 256, GEMM_SMEM>>>(
        Ahi, Alo, Wthf, Wtlf, out, bfc, nullptr, nullptr, NNODES, OUT_DIM, HC);
}

// round 15
// speedup vs baseline: 1.2887x; 1.0108x over previous
#include <cuda_runtime.h>
#include <cuda_bf16.h>
#include <cstdint>

// Problem constants (fixed by the dataset)
#define NNODES   50000
#define NEDGES   500000
#define IN_DIM   384
#define HID      128
#define HEADS    4
#define HC       (HEADS * HID)     // 512
#define OUT_DIM  384
#define NEG_SLOPE 0.2f
#define EPRIME   (NEDGES + NNODES) // edges + self loops

// ---------------------------------------------------------------------------
// Scratch (static device globals; allocation inside kernel_launch is banned)
// ---------------------------------------------------------------------------
__device__ float g_bufA[(size_t)NNODES * HC];                // GEMM output h
__device__ __align__(16) __nv_bfloat16 g_Ahi[(size_t)NNODES * HC];
__device__ __align__(16) __nv_bfloat16 g_Alo[(size_t)NNODES * HC];
// per-layer transposed weights (hi/lo)
__device__ __align__(16) __nv_bfloat16 g_Wth1[HC * IN_DIM];
__device__ __align__(16) __nv_bfloat16 g_Wtl1[HC * IN_DIM];
__device__ __align__(16) __nv_bfloat16 g_Wth2[HC * HC];
__device__ __align__(16) __nv_bfloat16 g_Wtl2[HC * HC];
__device__ __align__(16) __nv_bfloat16 g_Wthf[OUT_DIM * HC];
__device__ __align__(16) __nv_bfloat16 g_Wtlf[OUT_DIM * HC];
__device__ float g_asrc[NNODES * HEADS];
__device__ float g_adst[NNODES * HEADS];
// CSR (by dst) of the self-loop-augmented graph
__device__ int g_deg[NNODES];
__device__ int g_rowptr[NNODES];
__device__ int g_cursor[NNODES];
__device__ int g_csrc[EPRIME];
__device__ int g_bsums[256];

// ---------------------------------------------------------------------------
// Small PTX helpers (generic sm_80+ subset only — the bench's PTX stage is
// compute_103 (no 'a'), so no tcgen05/TMA instructions may appear here.)
// ---------------------------------------------------------------------------
__device__ __forceinline__ uint32_t smem_u32(const void* p) {
    uint32_t a;
    asm("{ .reg .u64 t; cvta.to.shared.u64 t, %1; cvt.u32.u64 %0, t; }"
        : "=r"(a) : "l"(p));
    return a;
}

__device__ __forceinline__ void cp_async16(uint32_t dst, const void* src, int srcBytes) {
    asm volatile("cp.async.cg.shared.global [%0], [%1], 16, %2;"
                 :: "r"(dst), "l"(src), "r"(srcBytes));
}
#define CP_ASYNC_COMMIT() asm volatile("cp.async.commit_group;" ::: "memory")
#define CP_ASYNC_WAIT(n)  asm volatile("cp.async.wait_group %0;" :: "n"(n) : "memory")

__device__ __forceinline__ void ldsm_x4(uint32_t* r, uint32_t addr) {
    asm volatile("ldmatrix.sync.aligned.m8n8.x4.shared.b16 {%0,%1,%2,%3}, [%4];"
                 : "=r"(r[0]), "=r"(r[1]), "=r"(r[2]), "=r"(r[3]) : "r"(addr));
}
__device__ __forceinline__ void ldsm_x2(uint32_t* r, uint32_t addr) {
    asm volatile("ldmatrix.sync.aligned.m8n8.x2.shared.b16 {%0,%1}, [%2];"
                 : "=r"(r[0]), "=r"(r[1]) : "r"(addr));
}

__device__ __forceinline__ void mma_bf16(float* c, const uint32_t* a, const uint32_t* b) {
    asm volatile(
        "mma.sync.aligned.m16n8k16.row.col.f32.bf16.bf16.f32 "
        "{%0,%1,%2,%3}, {%4,%5,%6,%7}, {%8,%9}, {%0,%1,%2,%3};"
        : "+f"(c[0]), "+f"(c[1]), "+f"(c[2]), "+f"(c[3])
        : "r"(a[0]), "r"(a[1]), "r"(a[2]), "r"(a[3]), "r"(b[0]), "r"(b[1]));
}

// ---------------------------------------------------------------------------
// bf16-split tensor-core GEMM:
//   C[M,N] = Ah@Bh^T + Ah@Bl^T + Al@Bh^T (+bias)
// Tile 128x128x32, 8 warps (warp tile 64x32), single __syncthreads per
// K-chunk, fused attn-scalar epilogue, __launch_bounds__(256, 2).
// PITCH=64 + per-row XOR chunk swizzle (conflict-free cp.async + ldmatrix).
// Round-15: 3-stage cp.async ring with wait_group(1) -> two chunks in
// flight; loads get two compute windows to cover DRAM latency
// (round 14: tensor=62.4% with depth-1 prefetch).
// 3 stages x 32KB x 2 blocks/SM = 192KB <= 228KB carveout.
// ---------------------------------------------------------------------------
#define PITCH      64                       // bytes per 32-bf16 row (no pad)
#define TILE_B     (128 * PITCH)            // 8192 B
#define STAGE_B    (4 * TILE_B)             // 32768 B (Ah, Al, Bh, Bl)
#define NSTAGE     3
#define GEMM_SMEM  (NSTAGE * STAGE_B)       // 98304 B

__global__ __launch_bounds__(256, 2)
void gemm_bf16_tc(const __nv_bfloat16* __restrict__ Ah,
                  const __nv_bfloat16* __restrict__ Al,
                  const __nv_bfloat16* __restrict__ Bh,
                  const __nv_bfloat16* __restrict__ Bl,
                  float* __restrict__ C, const float* __restrict__ bias,
                  const float* __restrict__ ws,   // att_src [HC] or null
                  const float* __restrict__ wd,   // att_dst [HC] or null
                  int M, int N, int K)
{
    extern __shared__ __align__(16) char smem[];
    const uint32_t sb = smem_u32(smem);
    const int tid  = threadIdx.x;
    const int wid  = tid >> 5, lane = tid & 31;
    const int wm   = wid >> 2, wn = wid & 3;      // warp grid 2x4
    const int g    = lane >> 2, q = lane & 3;
    const int m0   = blockIdx.y * 128, n0 = blockIdx.x * 128;
    const int KC   = K >> 5;

    // ldmatrix per-lane offsets (swizzled); invariant under mt/nt row bases
    const int arow   = lane & 15;
    const int achunk = lane >> 4;                 // 0/1
    const uint32_t aoff =
        (uint32_t)(arow * PITCH + ((achunk ^ ((arow >> 1) & 3)) << 4));
    const int brow   = lane & 7;
    const int bchunk = (lane >> 3) & 1;
    const uint32_t boff =
        (uint32_t)(brow * PITCH + ((bchunk ^ ((brow >> 1) & 3)) << 4));

    // async tile loader: 4 tiles of [128 x 32bf16], swizzled 16B stores
    auto load_chunk = [&](int kc, int st) {
        const int k0 = kc * 32;
        const uint32_t stb = sb + st * STAGE_B;
        #pragma unroll
        for (int t = 0; t < 4; t++) {
            const __nv_bfloat16* src =
                (t == 0) ? Ah : (t == 1) ? Al : (t == 2) ? Bh : Bl;
            const int  rbase = (t < 2) ? m0 : n0;
            const bool guard = (t < 2);
            const uint32_t tb = stb + t * TILE_B;
            #pragma unroll
            for (int i = 0; i < 2; i++) {
                int c16 = tid + i * 256;          // 0..511 chunk id
                int row = c16 >> 2, cw = c16 & 3; // 4 x 16B chunks per row
                int gr  = rbase + row;
                int ok  = (!guard || gr < M) ? 16 : 0;
                const __nv_bfloat16* s = src + (size_t)gr * K + k0 + cw * 8;
                uint32_t dst = tb + (uint32_t)(row * PITCH)
                             + (uint32_t)(((cw ^ ((row >> 1) & 3)) << 4));
                cp_async16(dst, s, ok);
            }
        }
    };

    float acc[4][4][4];
    #pragma unroll
    for (int i = 0; i < 4; i++)
        #pragma unroll
        for (int j = 0; j < 4; j++)
            #pragma unroll
            for (int r = 0; r < 4; r++) acc[i][j][r] = 0.f;

    // prologue: two chunks in flight
    load_chunk(0, 0);
    CP_ASYNC_COMMIT();
    if (KC > 1) {
        load_chunk(1, 1);
        CP_ASYNC_COMMIT();
    }

    for (int kc = 0; kc < KC; kc++) {
        if (kc + 1 < KC) {
            CP_ASYNC_WAIT(1);    // chunk kc resident; kc+1 may still fly
        } else {
            CP_ASYNC_WAIT(0);    // final chunk: drain all
        }
        __syncthreads();         // publishes stage kc; proves compute(kc-1) done
        if (kc + 2 < KC) {
            load_chunk(kc + 2, (kc + 2) % NSTAGE);
            CP_ASYNC_COMMIT();
        }

        const uint32_t stb = sb + (kc % NSTAGE) * STAGE_B;
        const uint32_t sAh = stb;
        const uint32_t sAl = stb + TILE_B;
        const uint32_t sBh = stb + 2 * TILE_B;
        const uint32_t sBl = stb + 3 * TILE_B;

        #pragma unroll
        for (int kt = 0; kt < 2; kt++) {
            const uint32_t ktx = (uint32_t)(kt << 5);   // XOR bit 5: chunks +2
            // B fragments for all 4 n-tiles (resident)
            uint32_t bh[4][2], bl[4][2];
            #pragma unroll
            for (int nt = 0; nt < 4; nt++) {
                uint32_t nb = (uint32_t)((wn * 32 + nt * 8) * PITCH);
                ldsm_x2(bh[nt], sBh + nb + (boff ^ ktx));
                ldsm_x2(bl[nt], sBl + nb + (boff ^ ktx));
            }
            #pragma unroll
            for (int mt = 0; mt < 4; mt++) {
                uint32_t mb = (uint32_t)((wm * 64 + mt * 16) * PITCH);
                uint32_t ah[4], al[4];
                ldsm_x4(ah, sAh + mb + (aoff ^ ktx));
                ldsm_x4(al, sAl + mb + (aoff ^ ktx));
                #pragma unroll
                for (int nt = 0; nt < 4; nt++) {
                    mma_bf16(acc[mt][nt], ah, bh[nt]);
                    mma_bf16(acc[mt][nt], ah, bl[nt]);
                    mma_bf16(acc[mt][nt], al, bh[nt]);
                }
            }
        }
    }

    // ---- store C (+ optional bias) ----
    #pragma unroll
    for (int mt = 0; mt < 4; mt++) {
        int r0 = m0 + wm * 64 + mt * 16 + g;
        #pragma unroll
        for (int nt = 0; nt < 4; nt++) {
            int cc = n0 + wn * 32 + nt * 8 + q * 2;
            float b0 = 0.f, b1 = 0.f;
            if (bias) { b0 = bias[cc]; b1 = bias[cc + 1]; }
            if (r0 < M) {
                float2 v = make_float2(acc[mt][nt][0] + b0, acc[mt][nt][1] + b1);
                *(float2*)(C + (size_t)r0 * N + cc) = v;
            }
            if (r0 + 8 < M) {
                float2 v = make_float2(acc[mt][nt][2] + b0, acc[mt][nt][3] + b1);
                *(float2*)(C + (size_t)(r0 + 8) * N + cc) = v;
            }
        }
    }

    // ---- fused attention scalars (GAT layers only) ----
    if (ws != nullptr) {
        __syncthreads();                        // done reading stages; reuse smem
        float* red = (float*)smem;              // [2][4][128] src/dst x wn x row
        float wsv[4][2], wdv[4][2];
        #pragma unroll
        for (int nt = 0; nt < 4; nt++) {
            int cc = n0 + wn * 32 + nt * 8 + q * 2;
            wsv[nt][0] = ws[cc];  wsv[nt][1] = ws[cc + 1];
            wdv[nt][0] = wd[cc];  wdv[nt][1] = wd[cc + 1];
        }
        #pragma unroll
        for (int mt = 0; mt < 4; mt++) {
            #pragma unroll
            for (int half = 0; half < 2; half++) {
                float ssrc = 0.f, sdst = 0.f;
                #pragma unroll
                for (int nt = 0; nt < 4; nt++) {
                    float v0 = acc[mt][nt][half * 2];
                    float v1 = acc[mt][nt][half * 2 + 1];
                    ssrc += v0 * wsv[nt][0] + v1 * wsv[nt][1];
                    sdst += v0 * wdv[nt][0] + v1 * wdv[nt][1];
                }
                ssrc += __shfl_xor_sync(0xffffffffu, ssrc, 1);
                ssrc += __shfl_xor_sync(0xffffffffu, ssrc, 2);
                sdst += __shfl_xor_sync(0xffffffffu, sdst, 1);
                sdst += __shfl_xor_sync(0xffffffffu, sdst, 2);
                if (q == 0) {
                    int rl = wm * 64 + mt * 16 + half * 8 + g;   // 0..127
                    red[(0 + wn) * 128 + rl] = ssrc;
                    red[(4 + wn) * 128 + rl] = sdst;
                }
            }
        }
        __syncthreads();
        int rl    = tid & 127;
        int which = tid >> 7;                   // 0 = src, 1 = dst
        const float* base = red + which * 4 * 128;
        float sum = base[0 * 128 + rl] + base[1 * 128 + rl]
                  + base[2 * 128 + rl] + base[3 * 128 + rl];
        int grow = m0 + rl;
        int head = n0 >> 7;                     // N-tile == head width
        if (grow < M) {
            float* dst = which ? g_adst : g_asrc;
            dst[grow * HEADS + head] = sum;
        }
    }
}

// ---------------------------------------------------------------------------
// Fused prep kernel 1: zero deg/cursor + all three weight transpose+splits.
// ---------------------------------------------------------------------------
__device__ __forceinline__ void wt_split_body(
    const float* __restrict__ W, __nv_bfloat16* __restrict__ Th,
    __nv_bfloat16* __restrict__ Tl, int K, int N, int bsub, int nsub)
{
    int i      = bsub * blockDim.x + threadIdx.x;
    int stride = nsub * blockDim.x;
    int total  = K * N;
    for (int j = i; j < total; j += stride) {
        int n = j % N, k = j / N;
        float f = W[(size_t)k * N + n];
        __nv_bfloat16 h = __float2bfloat16_rn(f);
        Th[(size_t)n * K + k] = h;
        Tl[(size_t)n * K + k] = __float2bfloat16_rn(f - __bfloat162float(h));
    }
}

__global__ __launch_bounds__(256)
void prep_weights(const float* __restrict__ W1, const float* __restrict__ W2,
                  const float* __restrict__ Wfc)
{
    int b = blockIdx.x;                       // 0..223
    if (b < 32) {
        for (int i = b * 256 + threadIdx.x; i < NNODES; i += 32 * 256) {
            g_deg[i] = 0;
            g_cursor[i] = 0;
        }
    } else if (b < 96) {
        wt_split_body(W1, g_Wth1, g_Wtl1, IN_DIM, HC, b - 32, 64);
    } else if (b < 160) {
        wt_split_body(W2, g_Wth2, g_Wtl2, HC, HC, b - 96, 64);
    } else {
        wt_split_body(Wfc, g_Wthf, g_Wtlf, HC, OUT_DIM, b - 160, 64);
    }
}

// ---------------------------------------------------------------------------
// Fused prep kernel 2: bf16 split of x + CSR degree count.  Grid = 1024.
// ---------------------------------------------------------------------------
__global__ __launch_bounds__(256)
void prep_x_count(const float* __restrict__ x, const int* __restrict__ ei)
{
    int b = blockIdx.x;                       // 0..1023
    if (b < 768) {
        const long n4 = (long)NNODES * IN_DIM / 4;
        long i      = (long)b * 256 + threadIdx.x;
        long stride = 768L * 256;
        for (long j = i; j < n4; j += stride) {
            float4 f = ((const float4*)x)[j];
            __nv_bfloat16 h0 = __float2bfloat16_rn(f.x);
            __nv_bfloat16 h1 = __float2bfloat16_rn(f.y);
            __nv_bfloat16 h2 = __float2bfloat16_rn(f.z);
            __nv_bfloat16 h3 = __float2bfloat16_rn(f.w);
            ((__nv_bfloat162*)g_Ahi)[j * 2]     = __nv_bfloat162{h0, h1};
            ((__nv_bfloat162*)g_Ahi)[j * 2 + 1] = __nv_bfloat162{h2, h3};
            ((__nv_bfloat162*)g_Alo)[j * 2] = __nv_bfloat162{
                __float2bfloat16_rn(f.x - __bfloat162float(h0)),
                __float2bfloat16_rn(f.y - __bfloat162float(h1))};
            ((__nv_bfloat162*)g_Alo)[j * 2 + 1] = __nv_bfloat162{
                __float2bfloat16_rn(f.z - __bfloat162float(h2)),
                __float2bfloat16_rn(f.w - __bfloat162float(h3))};
        }
    } else {
        for (int idx = (b - 768) * 256 + threadIdx.x; idx < EPRIME;
             idx += 256 * 256) {
            int d = (idx < NEDGES) ? ei[NEDGES + idx] : idx - NEDGES;
            atomicAdd(&g_deg[d], 1);
        }
    }
}

// ---------------------------------------------------------------------------
// CSR scan: chunk-local scan (scan1), then merged sums-scan + apply (scan23).
// ---------------------------------------------------------------------------
__global__ void csr_scan1()
{
    __shared__ int s[256];
    int t = threadIdx.x, idx = blockIdx.x * 256 + t;
    int val = (idx < NNODES) ? g_deg[idx] : 0;
    s[t] = val;
    __syncthreads();
    #pragma unroll
    for (int off = 1; off < 256; off <<= 1) {
        int v = (t >= off) ? s[t - off] : 0;
        __syncthreads();
        s[t] += v;
        __syncthreads();
    }
    if (idx < NNODES) g_rowptr[idx] = s[t] - val;   // exclusive within chunk
    if (t == 255) g_bsums[blockIdx.x] = s[255];
}

__global__ void csr_scan23(int nblk)
{
    __shared__ int s[256];
    int t = threadIdx.x;
    int val = (t < nblk) ? g_bsums[t] : 0;
    s[t] = val;
    __syncthreads();
    #pragma unroll
    for (int off = 1; off < 256; off <<= 1) {
        int v = (t >= off) ? s[t - off] : 0;
        __syncthreads();
        s[t] += v;
        __syncthreads();
    }
    int excl = s[blockIdx.x] - g_bsums[blockIdx.x]; // exclusive chunk offset
    int idx  = blockIdx.x * 256 + t;
    if (idx < NNODES) g_rowptr[idx] += excl;
}

__global__ void csr_scatter(const int* __restrict__ ei)
{
    int idx = blockIdx.x * blockDim.x + threadIdx.x;
    if (idx >= EPRIME) return;
    int s, d;
    if (idx < NEDGES) { s = ei[idx]; d = ei[NEDGES + idx]; }
    else              { s = d = idx - NEDGES; }
    int slot = g_rowptr[d] + atomicAdd(&g_cursor[d], 1);
    g_csrc[slot] = s;
}

// ---------------------------------------------------------------------------
// Fused GAT aggregation (unchanged): per-dst segment softmax + gather +
// bias + ReLU + bf16 hi/lo split.  One block (128 thr) per dst node;
// warp w = head w.  Register-cached fast path for deg <= 96.
// ---------------------------------------------------------------------------
#define AGG_CHUNK 64

__global__ __launch_bounds__(128)
void gat_aggregate(const float* __restrict__ h, const float* __restrict__ bias,
                   __nv_bfloat16* __restrict__ outHi,
                   __nv_bfloat16* __restrict__ outLo)
{
    __shared__ float s_alpha[HEADS][AGG_CHUNK];
    const int d    = blockIdx.x;
    const int tid  = threadIdx.x;
    const int head = tid >> 5, lane = tid & 31;
    const int beg  = g_rowptr[d];
    const int deg  = g_deg[d];
    const float adst = g_adst[d * HEADS + head];

    float4 acc = make_float4(0.f, 0.f, 0.f, 0.f);
    const float* hcol = h + tid * 4;               // column offset in row

    if (deg <= 96) {
        // ---- fast path: everything in registers, single gather pass ----
        int   se[3];
        float ve[3];
        #pragma unroll
        for (int c = 0; c < 3; c++) {
            int e = c * 32 + lane;
            if (e < deg) {
                int s = g_csrc[beg + e];
                float v = g_asrc[s * HEADS + head] + adst;
                ve[c] = v > 0.f ? v : NEG_SLOPE * v;
                se[c] = s;
            } else {
                se[c] = 0;
                ve[c] = -1e30f;
            }
        }
        float mx = fmaxf(ve[0], fmaxf(ve[1], ve[2]));
        #pragma unroll
        for (int o = 16; o > 0; o >>= 1)
            mx = fmaxf(mx, __shfl_xor_sync(0xffffffffu, mx, o));

        float ae[3];
        float sm = 0.f;
        #pragma unroll
        for (int c = 0; c < 3; c++) {
            float a = (c * 32 + lane < deg) ? __expf(ve[c] - mx) : 0.f;
            ae[c] = a;
            sm += a;
        }
        #pragma unroll
        for (int o = 16; o > 0; o >>= 1)
            sm += __shfl_xor_sync(0xffffffffu, sm, o);
        const float inv = 1.f / sm;

        #pragma unroll
        for (int c = 0; c < 3; c++) {
            int base = c * 32;
            if (base >= deg) break;
            int m = min(32, deg - base);
            int   sc = se[c];
            float ac = ae[c];
            #pragma unroll 4
            for (int l = 0; l < m; l++) {
                int   s = __shfl_sync(0xffffffffu, sc, l);
                float a = __shfl_sync(0xffffffffu, ac, l) * inv;
                float4 hv = *(const float4*)(hcol + (size_t)s * HC);
                acc.x += a * hv.x;
                acc.y += a * hv.y;
                acc.z += a * hv.z;
                acc.w += a * hv.w;
            }
        }
    } else {
        // ---- generic path (rare): 3-pass with smem alpha staging ----
        float mx = -1e30f;
        for (int e = lane; e < deg; e += 32) {
            int s = g_csrc[beg + e];
            float v = g_asrc[s * HEADS + head] + adst;
            v = v > 0.f ? v : NEG_SLOPE * v;
            mx = fmaxf(mx, v);
        }
        #pragma unroll
        for (int o = 16; o > 0; o >>= 1)
            mx = fmaxf(mx, __shfl_xor_sync(0xffffffffu, mx, o));

        float sm = 0.f;
        for (int e = lane; e < deg; e += 32) {
            int s = g_csrc[beg + e];
            float v = g_asrc[s * HEADS + head] + adst;
            v = v > 0.f ? v : NEG_SLOPE * v;
            sm += __expf(v - mx);
        }
        #pragma unroll
        for (int o = 16; o > 0; o >>= 1)
            sm += __shfl_xor_sync(0xffffffffu, sm, o);
        const float inv = 1.f / sm;

        for (int base = 0; base < deg; base += AGG_CHUNK) {
            int m = min(AGG_CHUNK, deg - base);
            for (int e = lane; e < m; e += 32) {
                int s = g_csrc[beg + base + e];
                float v = g_asrc[s * HEADS + head] + adst;
                v = v > 0.f ? v : NEG_SLOPE * v;
                s_alpha[head][e] = __expf(v - mx) * inv;
            }
            __syncwarp();
            #pragma unroll 4
            for (int e = 0; e < m; e++) {
                int s = g_csrc[beg + base + e];
                float a = s_alpha[head][e];
                float4 hv = *(const float4*)(hcol + (size_t)s * HC);
                acc.x += a * hv.x;
                acc.y += a * hv.y;
                acc.z += a * hv.z;
                acc.w += a * hv.w;
            }
            __syncwarp();
        }
    }

    // epilogue: bias + relu + bf16 split
    const float4 bv = *(const float4*)(bias + tid * 4);
    float o0 = fmaxf(acc.x + bv.x, 0.f);
    float o1 = fmaxf(acc.y + bv.y, 0.f);
    float o2 = fmaxf(acc.z + bv.z, 0.f);
    float o3 = fmaxf(acc.w + bv.w, 0.f);
    __nv_bfloat16 h0 = __float2bfloat16_rn(o0);
    __nv_bfloat16 h1 = __float2bfloat16_rn(o1);
    __nv_bfloat16 h2 = __float2bfloat16_rn(o2);
    __nv_bfloat16 h3 = __float2bfloat16_rn(o3);
    __nv_bfloat162* dh = (__nv_bfloat162*)(outHi + (size_t)d * HC + tid * 4);
    __nv_bfloat162* dl = (__nv_bfloat162*)(outLo + (size_t)d * HC + tid * 4);
    dh[0] = __nv_bfloat162{h0, h1};
    dh[1] = __nv_bfloat162{h2, h3};
    dl[0] = __nv_bfloat162{__float2bfloat16_rn(o0 - __bfloat162float(h0)),
                           __float2bfloat16_rn(o1 - __bfloat162float(h1))};
    dl[1] = __nv_bfloat162{__float2bfloat16_rn(o2 - __bfloat162float(h2)),
                           __float2bfloat16_rn(o3 - __bfloat162float(h3))};
}

// ---------------------------------------------------------------------------
// Host-side launch
// ---------------------------------------------------------------------------
extern "C" void kernel_launch(void* const* d_in, const int* in_sizes, int n_in,
                              void* d_out, int out_size)
{
    const float* x      = (const float*)d_in[0];
    const int*   ei     = (const int*)  d_in[1];
    const float* W1     = (const float*)d_in[2];
    const float* a1_src = (const float*)d_in[3];
    const float* a1_dst = (const float*)d_in[4];
    const float* b1     = (const float*)d_in[5];
    const float* W2     = (const float*)d_in[6];
    const float* a2_src = (const float*)d_in[7];
    const float* a2_dst = (const float*)d_in[8];
    const float* b2     = (const float*)d_in[9];
    const float* Wfc    = (const float*)d_in[10];
    const float* bfc    = (const float*)d_in[11];
    float* out = (float*)d_out;

    float* bufA;
    __nv_bfloat16 *Ahi, *Alo, *Wth1, *Wtl1, *Wth2, *Wtl2, *Wthf, *Wtlf;
    cudaGetSymbolAddress((void**)&bufA, g_bufA);
    cudaGetSymbolAddress((void**)&Ahi,  g_Ahi);
    cudaGetSymbolAddress((void**)&Alo,  g_Alo);
    cudaGetSymbolAddress((void**)&Wth1, g_Wth1);
    cudaGetSymbolAddress((void**)&Wtl1, g_Wtl1);
    cudaGetSymbolAddress((void**)&Wth2, g_Wth2);
    cudaGetSymbolAddress((void**)&Wtl2, g_Wtl2);
    cudaGetSymbolAddress((void**)&Wthf, g_Wthf);
    cudaGetSymbolAddress((void**)&Wtlf, g_Wtlf);

    cudaFuncSetAttribute(gemm_bf16_tc,
                         cudaFuncAttributeMaxDynamicSharedMemorySize, GEMM_SMEM);

    const int MB    = (NNODES + 127) / 128;       // 391
    const int eb    = (EPRIME + 255) / 256;
    const int nblk  = (NNODES + 255) / 256;       // 196 (scan chunks)

    // 1. zero deg/cursor + all weight splits (independent sections)
    prep_weights<<<224, 256>>>(W1, W2, Wfc);
    // 2. x bf16 split + CSR degree count (independent sections)
    prep_x_count<<<1024, 256>>>(x, ei);
    // 3. chunk-local rowptr scan
    csr_scan1<<<nblk, 256>>>();
    // 4. layer-1 GEMM (profiling slot)
    gemm_bf16_tc<<<dim3(HC / 128, MB), 256, GEMM_SMEM>>>(
        Ahi, Alo, Wth1, Wtl1, bufA, nullptr, a1_src, a1_dst, NNODES, HC, IN_DIM);
    // 5. merged sums-scan + apply
    csr_scan23<<<nblk, 256>>>(nblk);
    // 6. CSR scatter
    csr_scatter<<<eb, 256>>>(ei);
    // 7. layer-1 aggregate (softmax + gather + bias + relu + split)
    gat_aggregate<<<NNODES, 128>>>(bufA, b1, Ahi, Alo);

    // 8-9. layer 2
    gemm_bf16_tc<<<dim3(HC / 128, MB), 256, GEMM_SMEM>>>(
        Ahi, Alo, Wth2, Wtl2, bufA, nullptr, a2_src, a2_dst, NNODES, HC, HC);
    gat_aggregate<<<NNODES, 128>>>(bufA, b2, Ahi, Alo);

    // 10. FC head
    gemm_bf16_tc<<<dim3(OUT_DIM / 128, MB), 256, GEMM_SMEM>>>(
        Ahi, Alo, Wthf, Wtlf, out, bfc, nullptr, nullptr, NNODES, OUT_DIM, HC);
}